// round 10
// baseline (speedup 1.0000x reference)
#include <cuda_runtime.h>
#include <math.h>

#define BB   2
#define SS   768
#define DDIM 1024
#define HH   16
#define HDIM 64
#define NQh  8
#define NF   16
#define BHn  (BB*HH)     // 32
#define MM   (BB*SS)     // 1536
#define SPITCH 20
#define QKPITCH 84       // 84 % 32 == 20 -> conflict-free ldmatrix rows
#define VPITCH 68        // 68 % 32 == 4  -> conflict-free
#define ENTN2 895        // LUT span for 128-row q-tile

// ---------------- scratch ----------------------------------------------------
__device__ float g_Q[BHn*SS*HDIM];      // [bh][s][d]
__device__ float g_K[BHn*SS*HDIM];      // [bh][s][d]
__device__ float g_V[BHn*SS*HDIM];      // [bh][d][s]  (TRANSPOSED)
__device__ float g_fQ[BHn*SS*NF];
__device__ float g_fK[BHn*SS*NF];
__device__ float g_att[MM*DDIM];

// ---------------- helpers ----------------------------------------------------
__device__ __forceinline__ unsigned f2tf32(float f) {
    unsigned u;
    asm("cvt.rna.tf32.f32 %0, %1;" : "=r"(u) : "f"(f));
    return u;
}

__device__ __forceinline__ void mma_tf32(float& c0, float& c1, float& c2, float& c3,
                                         unsigned a0, unsigned a1, unsigned a2, unsigned a3,
                                         unsigned b0, unsigned b1) {
    asm volatile("mma.sync.aligned.m16n8k8.row.col.f32.tf32.tf32.f32 "
                 "{%0,%1,%2,%3}, {%4,%5,%6,%7}, {%8,%9}, {%0,%1,%2,%3};\n"
                 : "+f"(c0), "+f"(c1), "+f"(c2), "+f"(c3)
                 : "r"(a0), "r"(a1), "r"(a2), "r"(a3), "r"(b0), "r"(b1));
}

__device__ __forceinline__ void ldsm_x4(unsigned& r0, unsigned& r1,
                                        unsigned& r2, unsigned& r3, unsigned addr) {
    asm volatile("ldmatrix.sync.aligned.m8n8.x4.shared.b16 {%0,%1,%2,%3}, [%4];"
                 : "=r"(r0), "=r"(r1), "=r"(r2), "=r"(r3) : "r"(addr));
}

__device__ __forceinline__ void red_add_v2(float* p, float x, float y) {
    asm volatile("red.global.add.v2.f32 [%0], {%1,%2};"
                 :: "l"(p), "f"(x), "f"(y) : "memory");
}

// ============================================================================
// tf32 GEMM core for proj/outproj (unchanged)
// ============================================================================
#define GEMM_BODY(LOAD_A0, LOAD_A1, LOAD_B, NCHUNK)                              \
    float acc[4][4][4] = {};                                                     \
    int tid = threadIdx.x;                                                       \
    int wid = tid >> 5, lane = tid & 31;                                         \
    int wm = wid & 1, wnw = wid >> 1;                                            \
    int ar = tid >> 2, ac = (tid & 3) * 4;                                       \
    int bn = tid & 127, bk0 = (tid >> 7) * 8;                                    \
    int a_row = lane & 15, a_koff = (lane >> 4) * 4;                             \
    int b_nr  = (lane & 7) + ((lane >> 4) << 3);                                 \
    int b_koff = ((lane >> 3) & 1) * 4;                                          \
    unsigned aBase0 = (unsigned)__cvta_generic_to_shared(As0);                   \
    unsigned aBase1 = (unsigned)__cvta_generic_to_shared(As1);                   \
    unsigned bBase0 = (unsigned)__cvta_generic_to_shared(Bs0);                   \
    unsigned bBase1 = (unsigned)__cvta_generic_to_shared(Bs1);                   \
    float4 pa0, pa1; float pb[8];                                                \
    { int kg = 0;                                                                \
      pa0 = LOAD_A0(kg); pa1 = LOAD_A1(kg);                                      \
      _Pragma("unroll") for (int j = 0; j < 8; j++) pb[j] = LOAD_B(kg, j); }     \
    { unsigned* As = As0; unsigned* Bs = Bs0;                                    \
      *(uint4*)&As[ar * SPITCH + ac] =                                           \
          make_uint4(f2tf32(pa0.x), f2tf32(pa0.y), f2tf32(pa0.z), f2tf32(pa0.w));\
      *(uint4*)&As[(ar + 64) * SPITCH + ac] =                                    \
          make_uint4(f2tf32(pa1.x), f2tf32(pa1.y), f2tf32(pa1.z), f2tf32(pa1.w));\
      *(uint4*)&Bs[bn * SPITCH + bk0] =                                          \
          make_uint4(f2tf32(pb[0]), f2tf32(pb[1]), f2tf32(pb[2]), f2tf32(pb[3]));\
      *(uint4*)&Bs[bn * SPITCH + bk0 + 4] =                                      \
          make_uint4(f2tf32(pb[4]), f2tf32(pb[5]), f2tf32(pb[6]), f2tf32(pb[7]));}\
    __syncthreads();                                                             \
    for (int ch = 0; ch < (NCHUNK); ch++) {                                      \
        int buf = ch & 1;                                                        \
        if (ch + 1 < (NCHUNK)) {                                                 \
            int kg = (ch + 1) * 16;                                              \
            pa0 = LOAD_A0(kg); pa1 = LOAD_A1(kg);                                \
            _Pragma("unroll") for (int j = 0; j < 8; j++) pb[j] = LOAD_B(kg, j); \
        }                                                                        \
        unsigned aB = buf ? aBase1 : aBase0;                                     \
        unsigned bB = buf ? bBase1 : bBase0;                                     \
        _Pragma("unroll")                                                        \
        for (int ks = 0; ks < 2; ks++) {                                         \
            int kc = ks * 8;                                                     \
            unsigned af[4][4];                                                   \
            _Pragma("unroll")                                                    \
            for (int mt = 0; mt < 4; mt++)                                       \
                ldsm_x4(af[mt][0], af[mt][1], af[mt][2], af[mt][3],              \
                    aB + ((wm * 64 + mt * 16 + a_row) * SPITCH + kc + a_koff) * 4);\
            unsigned bf[4][2];                                                   \
            _Pragma("unroll")                                                    \
            for (int p = 0; p < 2; p++)                                          \
                ldsm_x4(bf[2 * p][0], bf[2 * p][1], bf[2 * p + 1][0],            \
                        bf[2 * p + 1][1],                                        \
                    bB + ((wnw * 32 + p * 16 + b_nr) * SPITCH + kc + b_koff) * 4);\
            _Pragma("unroll")                                                    \
            for (int mt = 0; mt < 4; mt++)                                       \
                _Pragma("unroll")                                                \
                for (int nt = 0; nt < 4; nt++)                                   \
                    mma_tf32(acc[mt][nt][0], acc[mt][nt][1],                     \
                             acc[mt][nt][2], acc[mt][nt][3],                     \
                             af[mt][0], af[mt][1], af[mt][2], af[mt][3],         \
                             bf[nt][0], bf[nt][1]);                              \
        }                                                                        \
        if (ch + 1 < (NCHUNK)) {                                                 \
            unsigned* As = buf ? As0 : As1;                                      \
            unsigned* Bs = buf ? Bs0 : Bs1;                                      \
            *(uint4*)&As[ar * SPITCH + ac] =                                     \
                make_uint4(f2tf32(pa0.x), f2tf32(pa0.y), f2tf32(pa0.z), f2tf32(pa0.w));\
            *(uint4*)&As[(ar + 64) * SPITCH + ac] =                              \
                make_uint4(f2tf32(pa1.x), f2tf32(pa1.y), f2tf32(pa1.z), f2tf32(pa1.w));\
            *(uint4*)&Bs[bn * SPITCH + bk0] =                                    \
                make_uint4(f2tf32(pb[0]), f2tf32(pb[1]), f2tf32(pb[2]), f2tf32(pb[3]));\
            *(uint4*)&Bs[bn * SPITCH + bk0 + 4] =                                \
                make_uint4(f2tf32(pb[4]), f2tf32(pb[5]), f2tf32(pb[6]), f2tf32(pb[7]));\
        }                                                                        \
        __syncthreads();                                                         \
    }

// ---------------- fused QKV projection ---------------------------------------
__global__ __launch_bounds__(256) void proj_kernel(
        const float* __restrict__ q, const float* __restrict__ k,
        const float* __restrict__ v,
        const float* __restrict__ Wq, const float* __restrict__ bq,
        const float* __restrict__ Wk, const float* __restrict__ bk,
        const float* __restrict__ Wv, const float* __restrict__ bv) {
    int which = blockIdx.z;
    const float* A    = (which == 0) ? q  : (which == 1) ? k  : v;
    const float* W    = (which == 0) ? Wq : (which == 1) ? Wk : Wv;
    const float* bias = (which == 0) ? bq : (which == 1) ? bk : bv;
    float*       out  = (which == 0) ? g_Q : (which == 1) ? g_K : g_V;

    __shared__ unsigned As0[128 * SPITCH], As1[128 * SPITCH];
    __shared__ unsigned Bs0[128 * SPITCH], Bs1[128 * SPITCH];
    int row0 = blockIdx.y * 128, col0 = blockIdx.x * 128;

#define LA0(kg) (*(const float4*)&A[(size_t)(row0 + ar) * DDIM + (kg) + ac])
#define LA1(kg) (*(const float4*)&A[(size_t)(row0 + 64 + ar) * DDIM + (kg) + ac])
#define LB(kg, j) (W[(size_t)((kg) + bk0 + (j)) * DDIM + col0 + bn])
    GEMM_BODY(LA0, LA1, LB, DDIM / 16)
#undef LA0
#undef LA1
#undef LB

    int g = lane >> 2, tg = lane & 3;
    #pragma unroll
    for (int mt = 0; mt < 4; mt++)
        #pragma unroll
        for (int nt = 0; nt < 4; nt++) {
            int gm = row0 + wm * 64 + mt * 16 + g;
            int gn = col0 + wnw * 32 + nt * 8 + tg * 2;
            #pragma unroll
            for (int hrow = 0; hrow < 2; hrow++) {
                int m = gm + hrow * 8;
                int b = m / SS, s = m % SS;
                int h = gn >> 6, d = gn & 63;
                if (which == 2) {
                    #pragma unroll
                    for (int j = 0; j < 2; j++)
                        out[((size_t)(b * HH + h) * HDIM + d + j) * SS + s] =
                            acc[mt][nt][hrow * 2 + j] + bias[gn + j];
                } else {
                    float2 st;
                    st.x = acc[mt][nt][hrow * 2]     + bias[gn];
                    st.y = acc[mt][nt][hrow * 2 + 1] + bias[gn + 1];
                    *(float2*)&out[((size_t)(b * HH + h) * SS + s) * HDIM + d] = st;
                }
            }
        }
}

// ---------------- out = attended @ Wo + bo -----------------------------------
__global__ __launch_bounds__(256) void outproj_kernel(const float* __restrict__ Wo,
                                                      const float* __restrict__ bo,
                                                      float* __restrict__ out) {
    __shared__ unsigned As0[128 * SPITCH], As1[128 * SPITCH];
    __shared__ unsigned Bs0[128 * SPITCH], Bs1[128 * SPITCH];
    int row0 = blockIdx.y * 128, col0 = blockIdx.x * 128;

#define LA0(kg) (*(const float4*)&g_att[(size_t)(row0 + ar) * DDIM + (kg) + ac])
#define LA1(kg) (*(const float4*)&g_att[(size_t)(row0 + 64 + ar) * DDIM + (kg) + ac])
#define LB(kg, j) (Wo[(size_t)((kg) + bk0 + (j)) * DDIM + col0 + bn])
    GEMM_BODY(LA0, LA1, LB, DDIM / 16)
#undef LA0
#undef LA1
#undef LB

    int g = lane >> 2, tg = lane & 3;
    #pragma unroll
    for (int mt = 0; mt < 4; mt++)
        #pragma unroll
        for (int nt = 0; nt < 4; nt++) {
            int gm = row0 + wm * 64 + mt * 16 + g;
            int gn = col0 + wnw * 32 + nt * 8 + tg * 2;
            #pragma unroll
            for (int hrow = 0; hrow < 2; hrow++) {
                int m = gm + hrow * 8;
                float2 st;
                st.x = acc[mt][nt][hrow * 2]     + bo[gn];
                st.y = acc[mt][nt][hrow * 2 + 1] + bo[gn + 1];
                *(float2*)&out[(size_t)m * DDIM + gn] = st;
            }
        }
}

// ---------------- quantum features (warp-per-row) ---------------------------
__global__ __launch_bounds__(256) void qfeat_kernel(
        const float* __restrict__ qmapW, const float* __restrict__ qmapb,
        const float* __restrict__ qw, const float* __restrict__ ph,
        const float* __restrict__ es_ptr) {
    int gw   = (blockIdx.x * blockDim.x + threadIdx.x) >> 5;
    int lane = threadIdx.x & 31;
    if (gw >= 2 * BHn * SS) return;
    int side = gw / (BHn * SS);
    int r    = gw % (BHn * SS);
    int h    = (r / SS) % HH;
    const float* row = ((side == 0) ? g_Q : g_K) + (size_t)r * HDIM;
    float rv0 = row[lane], rv1 = row[lane + 32];

    float mydot = 0.f;
    #pragma unroll
    for (int n = 0; n < NQh; n++) {
        float p = rv0 * qmapW[lane * NQh + n] + rv1 * qmapW[(lane + 32) * NQh + n];
        #pragma unroll
        for (int o = 16; o; o >>= 1) p += __shfl_xor_sync(0xffffffffu, p, o);
        if (lane == n) mydot = p;
    }
    if (lane < NQh) {
        float a = tanhf(mydot + qmapb[lane]);
        float s, c;
        if (side == 0) {
            float mix = 1.f / (1.f + __expf(-*es_ptr));
            float w = (1.f / (1.f + __expf(-qw[h * NQh + lane]))) * (1.0f / NQh) * mix;
            sincosf(a + ph[h * NQh + lane], &s, &c);
            g_fQ[(size_t)r * NF + lane]       = w * c;
            g_fQ[(size_t)r * NF + NQh + lane] = w * s;
        } else {
            sincosf(a, &s, &c);
            g_fK[(size_t)r * NF + lane]       = c;
            g_fK[(size_t)r * NF + NQh + lane] = s;
        }
    }
}

// ---------------- zero out2 --------------------------------------------------
__global__ void zero_out2_kernel(float* __restrict__ out2) {
    int idx = blockIdx.x * blockDim.x + threadIdx.x;
    if (idx < BB * SS * SS / 4)
        ((float4*)out2)[idx] = make_float4(0.f, 0.f, 0.f, 0.f);
}

// ---------------- flash attention v2: two-pass, register-resident -----------
// CTA: 128 q-rows, 256 threads (8 warps), warp owns 16 rows x full width.
// Pass 1: exact row stats (m, l). Pass 2: recompute scores, normalized probs
// -> red.add to out2 + shuffle-repack -> AV MMA. No P tile.
__global__ __launch_bounds__(256, 2) void attn2_kernel(const float* __restrict__ es_ptr,
                                                       float* __restrict__ out2) {
    extern __shared__ unsigned SMu[];
    unsigned* Qs = SMu;                       // [128][QKPITCH]
    unsigned* Ks = Qs + 128 * QKPITCH;        // [64][QKPITCH]
    unsigned* Vs = Ks + 64 * QKPITCH;         // [64][VPITCH]
    float*  entT = (float*)(Vs + 64 * VPITCH);// [ENTN2]

    int bh = blockIdx.y;
    int b = bh >> 4, h = bh & 15;
    int i0 = blockIdx.x * 128;
    const float* Qp  = g_Q  + (size_t)bh * SS * HDIM;
    const float* Kp  = g_K  + (size_t)bh * SS * HDIM;
    const float* Vtp = g_V  + (size_t)bh * HDIM * SS;
    const float* Fqp = g_fQ + (size_t)bh * SS * NF;
    const float* Fkp = g_fK + (size_t)bh * SS * NF;
    float* o2p = out2 + (size_t)b * SS * SS;

    int tid = threadIdx.x;
    int w = tid >> 5, lane = tid & 31;
    int g = lane >> 2, tg = lane & 3;
    int a_row = lane & 15, a_koff = (lane >> 4) * 4;
    int b_nr  = (lane & 7) + ((lane >> 4) << 3);
    int b_koff = ((lane >> 3) & 1) * 4;
    unsigned QsB = (unsigned)__cvta_generic_to_shared(Qs);
    unsigned KsB = (unsigned)__cvta_generic_to_shared(Ks);
    unsigned VsB = (unsigned)__cvta_generic_to_shared(Vs);

    float es  = *es_ptr;
    float mix = 1.f / (1.f + __expf(-es));
    float ca  = (1.f - mix) * 0.125f;

    // ent LUT: t = i_local + 767 - j  ->  |i - j| = |i0 + t - 767|
    for (int t = tid; t < ENTN2; t += 256)
        entT[t] = __expf(-0.1f * fabsf((float)(i0 + t - 767)));

    // stage Q*ca and Fq (once)
    #pragma unroll
    for (int it = 0; it < 8; it++) {
        int fid = tid + 256 * it;
        int r = fid >> 4, c4 = (fid & 15) * 4;
        float4 f = *(const float4*)&Qp[(size_t)(i0 + r) * HDIM + c4];
        *(uint4*)&Qs[r * QKPITCH + c4] =
            make_uint4(f2tf32(ca * f.x), f2tf32(ca * f.y),
                       f2tf32(ca * f.z), f2tf32(ca * f.w));
    }
    #pragma unroll
    for (int it = 0; it < 2; it++) {
        int fid = tid + 256 * it;
        int r = fid >> 2, c4 = (fid & 3) * 4;
        float4 f = *(const float4*)&Fqp[(size_t)(i0 + r) * NF + c4];
        *(uint4*)&Qs[r * QKPITCH + 64 + c4] =
            make_uint4(f2tf32(f.x), f2tf32(f.y), f2tf32(f.z), f2tf32(f.w));
    }

    float m0 = -1e30f, m1 = -1e30f, l0 = 0.f, l1 = 0.f;

    // ======================= PASS 1: row stats ==============================
    for (int jc = 0; jc < 12; jc++) {
        int j0 = jc * 64;
        __syncthreads();            // prior chunk's readers done
        #pragma unroll
        for (int it = 0; it < 4; it++) {
            int fid = tid + 256 * it;
            int r = fid >> 4, c4 = (fid & 15) * 4;
            float4 f = *(const float4*)&Kp[(size_t)(j0 + r) * HDIM + c4];
            *(uint4*)&Ks[r * QKPITCH + c4] =
                make_uint4(f2tf32(f.x), f2tf32(f.y), f2tf32(f.z), f2tf32(f.w));
        }
        {
            int r = tid >> 2, c4 = (tid & 3) * 4;
            float4 f = *(const float4*)&Fkp[(size_t)(j0 + r) * NF + c4];
            *(uint4*)&Ks[r * QKPITCH + 64 + c4] =
                make_uint4(f2tf32(f.x), f2tf32(f.y), f2tf32(f.z), f2tf32(f.w));
        }
        __syncthreads();

        float accC[8][4] = {}, accQ[8][4] = {};
        #pragma unroll
        for (int s = 0; s < 10; s++) {
            int kc = s * 8;
            unsigned qa[4];
            ldsm_x4(qa[0], qa[1], qa[2], qa[3],
                    QsB + ((w * 16 + a_row) * QKPITCH + kc + a_koff) * 4);
            unsigned bf[8][2];
            #pragma unroll
            for (int p = 0; p < 4; p++)
                ldsm_x4(bf[2 * p][0], bf[2 * p][1], bf[2 * p + 1][0], bf[2 * p + 1][1],
                        KsB + ((p * 16 + b_nr) * QKPITCH + kc + b_koff) * 4);
            #pragma unroll
            for (int nt = 0; nt < 8; nt++) {
                float* a = (s < 8) ? accC[nt] : accQ[nt];
                mma_tf32(a[0], a[1], a[2], a[3],
                         qa[0], qa[1], qa[2], qa[3], bf[nt][0], bf[nt][1]);
            }
        }
        // combine + stats
        float cmax0 = -1e30f, cmax1 = -1e30f;
        #pragma unroll
        for (int nt = 0; nt < 8; nt++) {
            #pragma unroll
            for (int e = 0; e < 4; e++) {
                int col  = j0 + nt * 8 + 2 * tg + (e & 1);
                int rowl = w * 16 + g + ((e >> 1) << 3);
                float sv = accC[nt][e] + entT[rowl + 767 - col] * accQ[nt][e];
                accC[nt][e] = sv;
                if (e < 2) cmax0 = fmaxf(cmax0, sv);
                else       cmax1 = fmaxf(cmax1, sv);
            }
        }
        #pragma unroll
        for (int o = 1; o < 4; o <<= 1) {
            cmax0 = fmaxf(cmax0, __shfl_xor_sync(0xffffffffu, cmax0, o));
            cmax1 = fmaxf(cmax1, __shfl_xor_sync(0xffffffffu, cmax1, o));
        }
        float nm0 = fmaxf(m0, cmax0), nm1 = fmaxf(m1, cmax1);
        float cs0 = 0.f, cs1 = 0.f;
        #pragma unroll
        for (int nt = 0; nt < 8; nt++) {
            cs0 += __expf(accC[nt][0] - nm0) + __expf(accC[nt][1] - nm0);
            cs1 += __expf(accC[nt][2] - nm1) + __expf(accC[nt][3] - nm1);
        }
        #pragma unroll
        for (int o = 1; o < 4; o <<= 1) {
            cs0 += __shfl_xor_sync(0xffffffffu, cs0, o);
            cs1 += __shfl_xor_sync(0xffffffffu, cs1, o);
        }
        l0 = l0 * __expf(m0 - nm0) + cs0;  m0 = nm0;
        l1 = l1 * __expf(m1 - nm1) + cs1;  m1 = nm1;
    }
    float invl0 = __frcp_rn(l0), invl1 = __frcp_rn(l1);

    // ======================= PASS 2: probs + AV =============================
    float O[8][4] = {};
    for (int jc = 0; jc < 12; jc++) {
        int j0 = jc * 64;
        __syncthreads();
        #pragma unroll
        for (int it = 0; it < 4; it++) {
            int fid = tid + 256 * it;
            int r = fid >> 4, c4 = (fid & 15) * 4;
            float4 f = *(const float4*)&Kp[(size_t)(j0 + r) * HDIM + c4];
            *(uint4*)&Ks[r * QKPITCH + c4] =
                make_uint4(f2tf32(f.x), f2tf32(f.y), f2tf32(f.z), f2tf32(f.w));
        }
        {
            int r = tid >> 2, c4 = (tid & 3) * 4;
            float4 f = *(const float4*)&Fkp[(size_t)(j0 + r) * NF + c4];
            *(uint4*)&Ks[r * QKPITCH + 64 + c4] =
                make_uint4(f2tf32(f.x), f2tf32(f.y), f2tf32(f.z), f2tf32(f.w));
        }
        #pragma unroll
        for (int it = 0; it < 4; it++) {
            int fid = tid + 256 * it;
            int d = fid >> 4, c4 = (fid & 15) * 4;
            float4 f = *(const float4*)&Vtp[(size_t)d * SS + j0 + c4];
            *(uint4*)&Vs[d * VPITCH + c4] =
                make_uint4(f2tf32(f.x), f2tf32(f.y), f2tf32(f.z), f2tf32(f.w));
        }
        __syncthreads();

        #pragma unroll
        for (int h2 = 0; h2 < 2; h2++) {
            float accC[4][4] = {}, accQ[4][4] = {};
            #pragma unroll
            for (int s = 0; s < 10; s++) {
                int kc = s * 8;
                unsigned qa[4];
                ldsm_x4(qa[0], qa[1], qa[2], qa[3],
                        QsB + ((w * 16 + a_row) * QKPITCH + kc + a_koff) * 4);
                unsigned bf[4][2];
                #pragma unroll
                for (int p = 0; p < 2; p++)
                    ldsm_x4(bf[2 * p][0], bf[2 * p][1], bf[2 * p + 1][0], bf[2 * p + 1][1],
                            KsB + ((h2 * 32 + p * 16 + b_nr) * QKPITCH + kc + b_koff) * 4);
                #pragma unroll
                for (int nt = 0; nt < 4; nt++) {
                    float* a = (s < 8) ? accC[nt] : accQ[nt];
                    mma_tf32(a[0], a[1], a[2], a[3],
                             qa[0], qa[1], qa[2], qa[3], bf[nt][0], bf[nt][1]);
                }
            }
            #pragma unroll
            for (int nn = 0; nn < 4; nn++) {
                // normalized probs for this 16x8 sub-block
                float p0, p1, p2, p3;
                {
                    int colb = j0 + h2 * 32 + nn * 8 + 2 * tg;
                    int r0 = w * 16 + g, r1 = r0 + 8;
                    p0 = __expf(accC[nn][0] + entT[r0 + 767 - colb]     * accQ[nn][0] - m0) * invl0;
                    p1 = __expf(accC[nn][1] + entT[r0 + 767 - colb - 1] * accQ[nn][1] - m0) * invl0;
                    p2 = __expf(accC[nn][2] + entT[r1 + 767 - colb]     * accQ[nn][2] - m1) * invl1;
                    p3 = __expf(accC[nn][3] + entT[r1 + 767 - colb - 1] * accQ[nn][3] - m1) * invl1;
                    // head-mean reduction
                    float* a0 = o2p + (size_t)(i0 + r0) * SS + colb;
                    float* a1 = o2p + (size_t)(i0 + r1) * SS + colb;
                    red_add_v2(a0, p0 * (1.0f / HH), p1 * (1.0f / HH));
                    red_add_v2(a1, p2 * (1.0f / HH), p3 * (1.0f / HH));
                }
                // repack C-frag -> A-frag:  a(g, tg) from c(g, 2*tgs+e)
                unsigned pa[4];
                {
                    int src1 = (lane & ~3) | (tg >> 1);
                    int src2 = src1 + 2;
                    float x0 = __shfl_sync(0xffffffffu, p0, src1);
                    float x1 = __shfl_sync(0xffffffffu, p1, src1);
                    float y0 = __shfl_sync(0xffffffffu, p0, src2);
                    float y1 = __shfl_sync(0xffffffffu, p1, src2);
                    pa[0] = f2tf32((tg & 1) ? x1 : x0);
                    pa[2] = f2tf32((tg & 1) ? y1 : y0);
                    float x2 = __shfl_sync(0xffffffffu, p2, src1);
                    float x3 = __shfl_sync(0xffffffffu, p3, src1);
                    float y2 = __shfl_sync(0xffffffffu, p2, src2);
                    float y3 = __shfl_sync(0xffffffffu, p3, src2);
                    pa[1] = f2tf32((tg & 1) ? x3 : x2);
                    pa[3] = f2tf32((tg & 1) ? y3 : y2);
                }
                // AV: O[16 x 64] += P[16 x 8] * V[8 x 64]
                int kk = h2 * 32 + nn * 8;
                unsigned bv[8][2];
                #pragma unroll
                for (int p = 0; p < 4; p++)
                    ldsm_x4(bv[2 * p][0], bv[2 * p][1], bv[2 * p + 1][0], bv[2 * p + 1][1],
                            VsB + ((p * 16 + b_nr) * VPITCH + kk + b_koff) * 4);
                #pragma unroll
                for (int dt = 0; dt < 8; dt++)
                    mma_tf32(O[dt][0], O[dt][1], O[dt][2], O[dt][3],
                             pa[0], pa[1], pa[2], pa[3], bv[dt][0], bv[dt][1]);
            }
        }
    }

    // epilogue -> g_att (probs were normalized; no division)
    #pragma unroll
    for (int dt = 0; dt < 8; dt++) {
        int d0 = dt * 8 + 2 * tg;
        int r0 = i0 + w * 16 + g;
        *(float2*)&g_att[(size_t)(b * SS + r0) * DDIM + h * HDIM + d0] =
            make_float2(O[dt][0], O[dt][1]);
        *(float2*)&g_att[(size_t)(b * SS + r0 + 8) * DDIM + h * HDIM + d0] =
            make_float2(O[dt][2], O[dt][3]);
    }
}

// ---------------- launch -----------------------------------------------------
extern "C" void kernel_launch(void* const* d_in, const int* in_sizes, int n_in,
                              void* d_out, int out_size) {
    const float* query = (const float*)d_in[0];
    const float* key   = (const float*)d_in[1];
    const float* value = (const float*)d_in[2];
    const float* Wq = (const float*)d_in[3];
    const float* bq = (const float*)d_in[4];
    const float* Wk = (const float*)d_in[5];
    const float* bk = (const float*)d_in[6];
    const float* Wv = (const float*)d_in[7];
    const float* bv = (const float*)d_in[8];
    const float* Wo = (const float*)d_in[9];
    const float* bo = (const float*)d_in[10];
    const float* qmapW = (const float*)d_in[11];
    const float* qmapb = (const float*)d_in[12];
    const float* qw    = (const float*)d_in[13];
    const float* ph    = (const float*)d_in[14];
    const float* es    = (const float*)d_in[15];

    float* out  = (float*)d_out;
    float* out2 = out + (size_t)MM * DDIM;

    {
        int n = BB * SS * SS / 4;
        zero_out2_kernel<<<(n + 255) / 256, 256>>>(out2);
    }
    proj_kernel<<<dim3(DDIM / 128, MM / 128, 3), 256>>>(query, key, value,
                                                        Wq, bq, Wk, bk, Wv, bv);
    {
        int nrows = 2 * BHn * SS;
        qfeat_kernel<<<nrows / 8, 256>>>(qmapW, qmapb, qw, ph, es);
    }
    {
        size_t smem = (size_t)(128 * QKPITCH + 64 * QKPITCH + 64 * VPITCH) * 4
                    + (size_t)ENTN2 * 4;   // 85500 B
        cudaFuncSetAttribute(attn2_kernel,
                             cudaFuncAttributeMaxDynamicSharedMemorySize, (int)smem);
        attn2_kernel<<<dim3(SS / 128, BHn), 256, smem>>>(es, out2);
    }
    outproj_kernel<<<dim3(DDIM / 128, MM / 128), 256>>>(Wo, bo, out);
}

// round 11
// speedup vs baseline: 1.0070x; 1.0070x over previous
#include <cuda_runtime.h>
#include <math.h>

#define BB   2
#define SS   768
#define DDIM 1024
#define HH   16
#define HDIM 64
#define NQh  8
#define NF   16
#define BHn  (BB*HH)     // 32
#define MM   (BB*SS)     // 1536
#define SPITCH 20
#define QKPITCH 84       // 84 % 32 == 20 -> conflict-free ldmatrix rows
#define VPITCH 68        // 68 % 32 == 4  -> conflict-free
#define ENTA 895         // LUT span, 128-row q-tile
#define ENTB 831         // LUT span, 64-row q-tile

// ---------------- scratch ----------------------------------------------------
__device__ float g_Q[BHn*SS*HDIM];      // [bh][s][d]
__device__ float g_K[BHn*SS*HDIM];      // [bh][s][d]
__device__ float g_V[BHn*SS*HDIM];      // [bh][d][s]  (TRANSPOSED)
__device__ float g_fQ[BHn*SS*NF];
__device__ float g_fK[BHn*SS*NF];
__device__ float g_att[MM*DDIM];
__device__ float g_stats[BHn*SS*2*2];   // [bh][row][split][{m,l}]

// ---------------- helpers ----------------------------------------------------
__device__ __forceinline__ unsigned f2tf32(float f) {
    unsigned u;
    asm("cvt.rna.tf32.f32 %0, %1;" : "=r"(u) : "f"(f));
    return u;
}

__device__ __forceinline__ void mma_tf32(float& c0, float& c1, float& c2, float& c3,
                                         unsigned a0, unsigned a1, unsigned a2, unsigned a3,
                                         unsigned b0, unsigned b1) {
    asm volatile("mma.sync.aligned.m16n8k8.row.col.f32.tf32.tf32.f32 "
                 "{%0,%1,%2,%3}, {%4,%5,%6,%7}, {%8,%9}, {%0,%1,%2,%3};\n"
                 : "+f"(c0), "+f"(c1), "+f"(c2), "+f"(c3)
                 : "r"(a0), "r"(a1), "r"(a2), "r"(a3), "r"(b0), "r"(b1));
}

__device__ __forceinline__ void ldsm_x4(unsigned& r0, unsigned& r1,
                                        unsigned& r2, unsigned& r3, unsigned addr) {
    asm volatile("ldmatrix.sync.aligned.m8n8.x4.shared.b16 {%0,%1,%2,%3}, [%4];"
                 : "=r"(r0), "=r"(r1), "=r"(r2), "=r"(r3) : "r"(addr));
}

__device__ __forceinline__ void red_add_v2(float* p, float x, float y) {
    asm volatile("red.global.add.v2.f32 [%0], {%1,%2};"
                 :: "l"(p), "f"(x), "f"(y) : "memory");
}

// ============================================================================
// tf32 GEMM core for proj/outproj (unchanged)
// ============================================================================
#define GEMM_BODY(LOAD_A0, LOAD_A1, LOAD_B, NCHUNK)                              \
    float acc[4][4][4] = {};                                                     \
    int tid = threadIdx.x;                                                       \
    int wid = tid >> 5, lane = tid & 31;                                         \
    int wm = wid & 1, wnw = wid >> 1;                                            \
    int ar = tid >> 2, ac = (tid & 3) * 4;                                       \
    int bn = tid & 127, bk0 = (tid >> 7) * 8;                                    \
    int a_row = lane & 15, a_koff = (lane >> 4) * 4;                             \
    int b_nr  = (lane & 7) + ((lane >> 4) << 3);                                 \
    int b_koff = ((lane >> 3) & 1) * 4;                                          \
    unsigned aBase0 = (unsigned)__cvta_generic_to_shared(As0);                   \
    unsigned aBase1 = (unsigned)__cvta_generic_to_shared(As1);                   \
    unsigned bBase0 = (unsigned)__cvta_generic_to_shared(Bs0);                   \
    unsigned bBase1 = (unsigned)__cvta_generic_to_shared(Bs1);                   \
    float4 pa0, pa1; float pb[8];                                                \
    { int kg = 0;                                                                \
      pa0 = LOAD_A0(kg); pa1 = LOAD_A1(kg);                                      \
      _Pragma("unroll") for (int j = 0; j < 8; j++) pb[j] = LOAD_B(kg, j); }     \
    { unsigned* As = As0; unsigned* Bs = Bs0;                                    \
      *(uint4*)&As[ar * SPITCH + ac] =                                           \
          make_uint4(f2tf32(pa0.x), f2tf32(pa0.y), f2tf32(pa0.z), f2tf32(pa0.w));\
      *(uint4*)&As[(ar + 64) * SPITCH + ac] =                                    \
          make_uint4(f2tf32(pa1.x), f2tf32(pa1.y), f2tf32(pa1.z), f2tf32(pa1.w));\
      *(uint4*)&Bs[bn * SPITCH + bk0] =                                          \
          make_uint4(f2tf32(pb[0]), f2tf32(pb[1]), f2tf32(pb[2]), f2tf32(pb[3]));\
      *(uint4*)&Bs[bn * SPITCH + bk0 + 4] =                                      \
          make_uint4(f2tf32(pb[4]), f2tf32(pb[5]), f2tf32(pb[6]), f2tf32(pb[7]));}\
    __syncthreads();                                                             \
    for (int ch = 0; ch < (NCHUNK); ch++) {                                      \
        int buf = ch & 1;                                                        \
        if (ch + 1 < (NCHUNK)) {                                                 \
            int kg = (ch + 1) * 16;                                              \
            pa0 = LOAD_A0(kg); pa1 = LOAD_A1(kg);                                \
            _Pragma("unroll") for (int j = 0; j < 8; j++) pb[j] = LOAD_B(kg, j); \
        }                                                                        \
        unsigned aB = buf ? aBase1 : aBase0;                                     \
        unsigned bB = buf ? bBase1 : bBase0;                                     \
        _Pragma("unroll")                                                        \
        for (int ks = 0; ks < 2; ks++) {                                         \
            int kc = ks * 8;                                                     \
            unsigned af[4][4];                                                   \
            _Pragma("unroll")                                                    \
            for (int mt = 0; mt < 4; mt++)                                       \
                ldsm_x4(af[mt][0], af[mt][1], af[mt][2], af[mt][3],              \
                    aB + ((wm * 64 + mt * 16 + a_row) * SPITCH + kc + a_koff) * 4);\
            unsigned bf[4][2];                                                   \
            _Pragma("unroll")                                                    \
            for (int p = 0; p < 2; p++)                                          \
                ldsm_x4(bf[2 * p][0], bf[2 * p][1], bf[2 * p + 1][0],            \
                        bf[2 * p + 1][1],                                        \
                    bB + ((wnw * 32 + p * 16 + b_nr) * SPITCH + kc + b_koff) * 4);\
            _Pragma("unroll")                                                    \
            for (int mt = 0; mt < 4; mt++)                                       \
                _Pragma("unroll")                                                \
                for (int nt = 0; nt < 4; nt++)                                   \
                    mma_tf32(acc[mt][nt][0], acc[mt][nt][1],                     \
                             acc[mt][nt][2], acc[mt][nt][3],                     \
                             af[mt][0], af[mt][1], af[mt][2], af[mt][3],         \
                             bf[nt][0], bf[nt][1]);                              \
        }                                                                        \
        if (ch + 1 < (NCHUNK)) {                                                 \
            unsigned* As = buf ? As0 : As1;                                      \
            unsigned* Bs = buf ? Bs0 : Bs1;                                      \
            *(uint4*)&As[ar * SPITCH + ac] =                                     \
                make_uint4(f2tf32(pa0.x), f2tf32(pa0.y), f2tf32(pa0.z), f2tf32(pa0.w));\
            *(uint4*)&As[(ar + 64) * SPITCH + ac] =                              \
                make_uint4(f2tf32(pa1.x), f2tf32(pa1.y), f2tf32(pa1.z), f2tf32(pa1.w));\
            *(uint4*)&Bs[bn * SPITCH + bk0] =                                    \
                make_uint4(f2tf32(pb[0]), f2tf32(pb[1]), f2tf32(pb[2]), f2tf32(pb[3]));\
            *(uint4*)&Bs[bn * SPITCH + bk0 + 4] =                                \
                make_uint4(f2tf32(pb[4]), f2tf32(pb[5]), f2tf32(pb[6]), f2tf32(pb[7]));\
        }                                                                        \
        __syncthreads();                                                         \
    }

// ---------------- fused QKV projection ---------------------------------------
__global__ __launch_bounds__(256) void proj_kernel(
        const float* __restrict__ q, const float* __restrict__ k,
        const float* __restrict__ v,
        const float* __restrict__ Wq, const float* __restrict__ bq,
        const float* __restrict__ Wk, const float* __restrict__ bk,
        const float* __restrict__ Wv, const float* __restrict__ bv) {
    int which = blockIdx.z;
    const float* A    = (which == 0) ? q  : (which == 1) ? k  : v;
    const float* W    = (which == 0) ? Wq : (which == 1) ? Wk : Wv;
    const float* bias = (which == 0) ? bq : (which == 1) ? bk : bv;
    float*       out  = (which == 0) ? g_Q : (which == 1) ? g_K : g_V;

    __shared__ unsigned As0[128 * SPITCH], As1[128 * SPITCH];
    __shared__ unsigned Bs0[128 * SPITCH], Bs1[128 * SPITCH];
    int row0 = blockIdx.y * 128, col0 = blockIdx.x * 128;

#define LA0(kg) (*(const float4*)&A[(size_t)(row0 + ar) * DDIM + (kg) + ac])
#define LA1(kg) (*(const float4*)&A[(size_t)(row0 + 64 + ar) * DDIM + (kg) + ac])
#define LB(kg, j) (W[(size_t)((kg) + bk0 + (j)) * DDIM + col0 + bn])
    GEMM_BODY(LA0, LA1, LB, DDIM / 16)
#undef LA0
#undef LA1
#undef LB

    int g = lane >> 2, tg = lane & 3;
    #pragma unroll
    for (int mt = 0; mt < 4; mt++)
        #pragma unroll
        for (int nt = 0; nt < 4; nt++) {
            int gm = row0 + wm * 64 + mt * 16 + g;
            int gn = col0 + wnw * 32 + nt * 8 + tg * 2;
            #pragma unroll
            for (int hrow = 0; hrow < 2; hrow++) {
                int m = gm + hrow * 8;
                int b = m / SS, s = m % SS;
                int h = gn >> 6, d = gn & 63;
                if (which == 2) {
                    #pragma unroll
                    for (int j = 0; j < 2; j++)
                        out[((size_t)(b * HH + h) * HDIM + d + j) * SS + s] =
                            acc[mt][nt][hrow * 2 + j] + bias[gn + j];
                } else {
                    float2 st;
                    st.x = acc[mt][nt][hrow * 2]     + bias[gn];
                    st.y = acc[mt][nt][hrow * 2 + 1] + bias[gn + 1];
                    *(float2*)&out[((size_t)(b * HH + h) * SS + s) * HDIM + d] = st;
                }
            }
        }
}

// ---------------- out = attended @ Wo + bo -----------------------------------
__global__ __launch_bounds__(256) void outproj_kernel(const float* __restrict__ Wo,
                                                      const float* __restrict__ bo,
                                                      float* __restrict__ out) {
    __shared__ unsigned As0[128 * SPITCH], As1[128 * SPITCH];
    __shared__ unsigned Bs0[128 * SPITCH], Bs1[128 * SPITCH];
    int row0 = blockIdx.y * 128, col0 = blockIdx.x * 128;

#define LA0(kg) (*(const float4*)&g_att[(size_t)(row0 + ar) * DDIM + (kg) + ac])
#define LA1(kg) (*(const float4*)&g_att[(size_t)(row0 + 64 + ar) * DDIM + (kg) + ac])
#define LB(kg, j) (Wo[(size_t)((kg) + bk0 + (j)) * DDIM + col0 + bn])
    GEMM_BODY(LA0, LA1, LB, DDIM / 16)
#undef LA0
#undef LA1
#undef LB

    int g = lane >> 2, tg = lane & 3;
    #pragma unroll
    for (int mt = 0; mt < 4; mt++)
        #pragma unroll
        for (int nt = 0; nt < 4; nt++) {
            int gm = row0 + wm * 64 + mt * 16 + g;
            int gn = col0 + wnw * 32 + nt * 8 + tg * 2;
            #pragma unroll
            for (int hrow = 0; hrow < 2; hrow++) {
                int m = gm + hrow * 8;
                float2 st;
                st.x = acc[mt][nt][hrow * 2]     + bo[gn];
                st.y = acc[mt][nt][hrow * 2 + 1] + bo[gn + 1];
                *(float2*)&out[(size_t)m * DDIM + gn] = st;
            }
        }
}

// ---------------- quantum features (warp-per-row) ---------------------------
__global__ __launch_bounds__(256) void qfeat_kernel(
        const float* __restrict__ qmapW, const float* __restrict__ qmapb,
        const float* __restrict__ qw, const float* __restrict__ ph,
        const float* __restrict__ es_ptr) {
    int gw   = (blockIdx.x * blockDim.x + threadIdx.x) >> 5;
    int lane = threadIdx.x & 31;
    if (gw >= 2 * BHn * SS) return;
    int side = gw / (BHn * SS);
    int r    = gw % (BHn * SS);
    int h    = (r / SS) % HH;
    const float* row = ((side == 0) ? g_Q : g_K) + (size_t)r * HDIM;
    float rv0 = row[lane], rv1 = row[lane + 32];

    float mydot = 0.f;
    #pragma unroll
    for (int n = 0; n < NQh; n++) {
        float p = rv0 * qmapW[lane * NQh + n] + rv1 * qmapW[(lane + 32) * NQh + n];
        #pragma unroll
        for (int o = 16; o; o >>= 1) p += __shfl_xor_sync(0xffffffffu, p, o);
        if (lane == n) mydot = p;
    }
    if (lane < NQh) {
        float a = tanhf(mydot + qmapb[lane]);
        float s, c;
        if (side == 0) {
            float mix = 1.f / (1.f + __expf(-*es_ptr));
            float w = (1.f / (1.f + __expf(-qw[h * NQh + lane]))) * (1.0f / NQh) * mix;
            sincosf(a + ph[h * NQh + lane], &s, &c);
            g_fQ[(size_t)r * NF + lane]       = w * c;
            g_fQ[(size_t)r * NF + NQh + lane] = w * s;
        } else {
            sincosf(a, &s, &c);
            g_fK[(size_t)r * NF + lane]       = c;
            g_fK[(size_t)r * NF + NQh + lane] = s;
        }
    }
}

// ---------------- zero out2 + g_att ------------------------------------------
__global__ void zero_kernel(float* __restrict__ out2) {
    int idx = blockIdx.x * blockDim.x + threadIdx.x;
    int n2 = BB * SS * SS / 4;
    if (idx < n2)
        ((float4*)out2)[idx] = make_float4(0.f, 0.f, 0.f, 0.f);
    int na = MM * DDIM / 4;
    if (idx < na)
        ((float4*)g_att)[idx] = make_float4(0.f, 0.f, 0.f, 0.f);
}

// ---------------- attnA: partial softmax stats (m,l) per k-split ------------
// grid (SS/128, BHn, 2). 256 thr, warp owns 16 rows x 64-col chunks.
__global__ __launch_bounds__(256, 2) void attnA_kernel(const float* __restrict__ es_ptr) {
    extern __shared__ unsigned SMu[];
    unsigned* Qs = SMu;                        // [128][QKPITCH]
    unsigned* Ks = Qs + 128 * QKPITCH;         // [64][QKPITCH]
    float*  entT = (float*)(Ks + 64 * QKPITCH);// [ENTA]

    int bh = blockIdx.y;
    int i0 = blockIdx.x * 128;
    int split = blockIdx.z;
    int jbase = split * 384;
    const float* Qp  = g_Q  + (size_t)bh * SS * HDIM;
    const float* Kp  = g_K  + (size_t)bh * SS * HDIM;
    const float* Fqp = g_fQ + (size_t)bh * SS * NF;
    const float* Fkp = g_fK + (size_t)bh * SS * NF;

    int tid = threadIdx.x;
    int w = tid >> 5, lane = tid & 31;
    int g = lane >> 2, tg = lane & 3;
    int a_row = lane & 15, a_koff = (lane >> 4) * 4;
    int b_nr  = (lane & 7) + ((lane >> 4) << 3);
    int b_koff = ((lane >> 3) & 1) * 4;
    unsigned QsB = (unsigned)__cvta_generic_to_shared(Qs);
    unsigned KsB = (unsigned)__cvta_generic_to_shared(Ks);

    float es  = *es_ptr;
    float mix = 1.f / (1.f + __expf(-es));
    float ca  = (1.f - mix) * 0.125f;

    for (int t = tid; t < ENTA; t += 256)
        entT[t] = __expf(-0.1f * fabsf((float)(i0 + t - 767)));

    #pragma unroll
    for (int it = 0; it < 8; it++) {
        int fid = tid + 256 * it;
        int r = fid >> 4, c4 = (fid & 15) * 4;
        float4 f = *(const float4*)&Qp[(size_t)(i0 + r) * HDIM + c4];
        *(uint4*)&Qs[r * QKPITCH + c4] =
            make_uint4(f2tf32(ca * f.x), f2tf32(ca * f.y),
                       f2tf32(ca * f.z), f2tf32(ca * f.w));
    }
    #pragma unroll
    for (int it = 0; it < 2; it++) {
        int fid = tid + 256 * it;
        int r = fid >> 2, c4 = (fid & 3) * 4;
        float4 f = *(const float4*)&Fqp[(size_t)(i0 + r) * NF + c4];
        *(uint4*)&Qs[r * QKPITCH + 64 + c4] =
            make_uint4(f2tf32(f.x), f2tf32(f.y), f2tf32(f.z), f2tf32(f.w));
    }

    float m0 = -1e30f, m1 = -1e30f, l0 = 0.f, l1 = 0.f;

    for (int jc = 0; jc < 6; jc++) {
        int j0 = jbase + jc * 64;
        __syncthreads();
        #pragma unroll
        for (int it = 0; it < 4; it++) {
            int fid = tid + 256 * it;
            int r = fid >> 4, c4 = (fid & 15) * 4;
            float4 f = *(const float4*)&Kp[(size_t)(j0 + r) * HDIM + c4];
            *(uint4*)&Ks[r * QKPITCH + c4] =
                make_uint4(f2tf32(f.x), f2tf32(f.y), f2tf32(f.z), f2tf32(f.w));
        }
        {
            int r = tid >> 2, c4 = (tid & 3) * 4;
            float4 f = *(const float4*)&Fkp[(size_t)(j0 + r) * NF + c4];
            *(uint4*)&Ks[r * QKPITCH + 64 + c4] =
                make_uint4(f2tf32(f.x), f2tf32(f.y), f2tf32(f.z), f2tf32(f.w));
        }
        __syncthreads();

        float accC[8][4] = {}, accQ[8][4] = {};
        #pragma unroll
        for (int s = 0; s < 10; s++) {
            int kc = s * 8;
            unsigned qa[4];
            ldsm_x4(qa[0], qa[1], qa[2], qa[3],
                    QsB + ((w * 16 + a_row) * QKPITCH + kc + a_koff) * 4);
            unsigned bf[8][2];
            #pragma unroll
            for (int p = 0; p < 4; p++)
                ldsm_x4(bf[2 * p][0], bf[2 * p][1], bf[2 * p + 1][0], bf[2 * p + 1][1],
                        KsB + ((p * 16 + b_nr) * QKPITCH + kc + b_koff) * 4);
            #pragma unroll
            for (int nt = 0; nt < 8; nt++) {
                float* a = (s < 8) ? accC[nt] : accQ[nt];
                mma_tf32(a[0], a[1], a[2], a[3],
                         qa[0], qa[1], qa[2], qa[3], bf[nt][0], bf[nt][1]);
            }
        }
        float cmax0 = -1e30f, cmax1 = -1e30f;
        #pragma unroll
        for (int nt = 0; nt < 8; nt++) {
            #pragma unroll
            for (int e = 0; e < 4; e++) {
                int col  = j0 + nt * 8 + 2 * tg + (e & 1);
                int rowl = w * 16 + g + ((e >> 1) << 3);
                float sv = accC[nt][e] + entT[rowl + 767 - col] * accQ[nt][e];
                accC[nt][e] = sv;
                if (e < 2) cmax0 = fmaxf(cmax0, sv);
                else       cmax1 = fmaxf(cmax1, sv);
            }
        }
        #pragma unroll
        for (int o = 1; o < 4; o <<= 1) {
            cmax0 = fmaxf(cmax0, __shfl_xor_sync(0xffffffffu, cmax0, o));
            cmax1 = fmaxf(cmax1, __shfl_xor_sync(0xffffffffu, cmax1, o));
        }
        float nm0 = fmaxf(m0, cmax0), nm1 = fmaxf(m1, cmax1);
        float cs0 = 0.f, cs1 = 0.f;
        #pragma unroll
        for (int nt = 0; nt < 8; nt++) {
            cs0 += __expf(accC[nt][0] - nm0) + __expf(accC[nt][1] - nm0);
            cs1 += __expf(accC[nt][2] - nm1) + __expf(accC[nt][3] - nm1);
        }
        #pragma unroll
        for (int o = 1; o < 4; o <<= 1) {
            cs0 += __shfl_xor_sync(0xffffffffu, cs0, o);
            cs1 += __shfl_xor_sync(0xffffffffu, cs1, o);
        }
        l0 = l0 * __expf(m0 - nm0) + cs0;  m0 = nm0;
        l1 = l1 * __expf(m1 - nm1) + cs1;  m1 = nm1;
    }

    if (tg == 0) {
        int gr0 = i0 + w * 16 + g;
        *(float2*)&g_stats[((size_t)(bh * SS + gr0) * 2 + split) * 2] =
            make_float2(m0, l0);
        *(float2*)&g_stats[((size_t)(bh * SS + gr0 + 8) * 2 + split) * 2] =
            make_float2(m1, l1);
    }
}

// ---------------- attnB: probs (out2) + AV (g_att), k-split ------------------
// grid (SS/64, BHn, 2). 256 thr, 8 warps = 4m x 2n; warp = 16 rows x 32 cols.
__global__ __launch_bounds__(256, 2) void attnB_kernel(const float* __restrict__ es_ptr,
                                                       float* __restrict__ out2) {
    extern __shared__ unsigned SMu[];
    unsigned* Qs = SMu;                        // [64][QKPITCH]
    unsigned* Ks = Qs + 64 * QKPITCH;          // [64][QKPITCH]
    unsigned* Vs = Ks + 64 * QKPITCH;          // [64][VPITCH]
    float*  entT = (float*)(Vs + 64 * VPITCH); // [ENTB]

    int bh = blockIdx.y;
    int b = bh >> 4, h = bh & 15;
    int i0 = blockIdx.x * 64;
    int split = blockIdx.z;
    int jbase = split * 384;
    const float* Qp  = g_Q  + (size_t)bh * SS * HDIM;
    const float* Kp  = g_K  + (size_t)bh * SS * HDIM;
    const float* Vtp = g_V  + (size_t)bh * HDIM * SS;
    const float* Fqp = g_fQ + (size_t)bh * SS * NF;
    const float* Fkp = g_fK + (size_t)bh * SS * NF;
    float* o2p = out2 + (size_t)b * SS * SS;

    int tid = threadIdx.x;
    int wid = tid >> 5, lane = tid & 31;
    int wm = wid & 3, wn = wid >> 2;
    int g = lane >> 2, tg = lane & 3;
    int a_row = lane & 15, a_koff = (lane >> 4) * 4;
    int b_nr  = (lane & 7) + ((lane >> 4) << 3);
    int b_koff = ((lane >> 3) & 1) * 4;
    unsigned QsB = (unsigned)__cvta_generic_to_shared(Qs);
    unsigned KsB = (unsigned)__cvta_generic_to_shared(Ks);
    unsigned VsB = (unsigned)__cvta_generic_to_shared(Vs);

    float es  = *es_ptr;
    float mix = 1.f / (1.f + __expf(-es));
    float ca  = (1.f - mix) * 0.125f;

    for (int t = tid; t < ENTB; t += 256)
        entT[t] = __expf(-0.1f * fabsf((float)(i0 + t - 767)));

    // stage Qs (64 rows) + Fq
    #pragma unroll
    for (int it = 0; it < 4; it++) {
        int fid = tid + 256 * it;
        int r = fid >> 4, c4 = (fid & 15) * 4;
        float4 f = *(const float4*)&Qp[(size_t)(i0 + r) * HDIM + c4];
        *(uint4*)&Qs[r * QKPITCH + c4] =
            make_uint4(f2tf32(ca * f.x), f2tf32(ca * f.y),
                       f2tf32(ca * f.z), f2tf32(ca * f.w));
    }
    {
        int r = tid >> 2, c4 = (tid & 3) * 4;
        float4 f = *(const float4*)&Fqp[(size_t)(i0 + r) * NF + c4];
        *(uint4*)&Qs[r * QKPITCH + 64 + c4] =
            make_uint4(f2tf32(f.x), f2tf32(f.y), f2tf32(f.z), f2tf32(f.w));
    }

    // combine stats from both splits (final m,l per owned row)
    float m0, m1, invl0, invl1;
    {
        int gr0 = i0 + wm * 16 + g;
        float2 sA = *(const float2*)&g_stats[((size_t)(bh * SS + gr0) * 2 + 0) * 2];
        float2 sB = *(const float2*)&g_stats[((size_t)(bh * SS + gr0) * 2 + 1) * 2];
        m0 = fmaxf(sA.x, sB.x);
        invl0 = __frcp_rn(sA.y * __expf(sA.x - m0) + sB.y * __expf(sB.x - m0));
        float2 tA = *(const float2*)&g_stats[((size_t)(bh * SS + gr0 + 8) * 2 + 0) * 2];
        float2 tB = *(const float2*)&g_stats[((size_t)(bh * SS + gr0 + 8) * 2 + 1) * 2];
        m1 = fmaxf(tA.x, tB.x);
        invl1 = __frcp_rn(tA.y * __expf(tA.x - m1) + tB.y * __expf(tB.x - m1));
    }

    float O[8][4] = {};
    for (int jc = 0; jc < 6; jc++) {
        int j0 = jbase + jc * 64;
        __syncthreads();
        #pragma unroll
        for (int it = 0; it < 4; it++) {
            int fid = tid + 256 * it;
            int r = fid >> 4, c4 = (fid & 15) * 4;
            float4 f = *(const float4*)&Kp[(size_t)(j0 + r) * HDIM + c4];
            *(uint4*)&Ks[r * QKPITCH + c4] =
                make_uint4(f2tf32(f.x), f2tf32(f.y), f2tf32(f.z), f2tf32(f.w));
        }
        {
            int r = tid >> 2, c4 = (tid & 3) * 4;
            float4 f = *(const float4*)&Fkp[(size_t)(j0 + r) * NF + c4];
            *(uint4*)&Ks[r * QKPITCH + 64 + c4] =
                make_uint4(f2tf32(f.x), f2tf32(f.y), f2tf32(f.z), f2tf32(f.w));
        }
        #pragma unroll
        for (int it = 0; it < 4; it++) {
            int fid = tid + 256 * it;
            int d = fid >> 4, c4 = (fid & 15) * 4;
            float4 f = *(const float4*)&Vtp[(size_t)d * SS + j0 + c4];
            *(uint4*)&Vs[d * VPITCH + c4] =
                make_uint4(f2tf32(f.x), f2tf32(f.y), f2tf32(f.z), f2tf32(f.w));
        }
        __syncthreads();

        // scores: warp 16 rows x 32 cols (cols wn*32 + [0,32))
        float accC[4][4] = {}, accQ[4][4] = {};
        #pragma unroll
        for (int s = 0; s < 10; s++) {
            int kc = s * 8;
            unsigned qa[4];
            ldsm_x4(qa[0], qa[1], qa[2], qa[3],
                    QsB + ((wm * 16 + a_row) * QKPITCH + kc + a_koff) * 4);
            unsigned bf[4][2];
            #pragma unroll
            for (int p = 0; p < 2; p++)
                ldsm_x4(bf[2 * p][0], bf[2 * p][1], bf[2 * p + 1][0], bf[2 * p + 1][1],
                        KsB + ((wn * 32 + p * 16 + b_nr) * QKPITCH + kc + b_koff) * 4);
            #pragma unroll
            for (int nt = 0; nt < 4; nt++) {
                float* a = (s < 8) ? accC[nt] : accQ[nt];
                mma_tf32(a[0], a[1], a[2], a[3],
                         qa[0], qa[1], qa[2], qa[3], bf[nt][0], bf[nt][1]);
            }
        }
        #pragma unroll
        for (int nn = 0; nn < 4; nn++) {
            float p0, p1, p2, p3;
            {
                int colb = j0 + wn * 32 + nn * 8 + 2 * tg;
                int r0 = wm * 16 + g, r1 = r0 + 8;
                p0 = __expf(accC[nn][0] + entT[r0 + 767 - colb]     * accQ[nn][0] - m0) * invl0;
                p1 = __expf(accC[nn][1] + entT[r0 + 767 - colb - 1] * accQ[nn][1] - m0) * invl0;
                p2 = __expf(accC[nn][2] + entT[r1 + 767 - colb]     * accQ[nn][2] - m1) * invl1;
                p3 = __expf(accC[nn][3] + entT[r1 + 767 - colb - 1] * accQ[nn][3] - m1) * invl1;
                float* a0 = o2p + (size_t)(i0 + r0) * SS + colb;
                float* a1 = o2p + (size_t)(i0 + r1) * SS + colb;
                red_add_v2(a0, p0 * (1.0f / HH), p1 * (1.0f / HH));
                red_add_v2(a1, p2 * (1.0f / HH), p3 * (1.0f / HH));
            }
            unsigned pa[4];
            {
                int src1 = (lane & ~3) | (tg >> 1);
                int src2 = src1 + 2;
                float x0 = __shfl_sync(0xffffffffu, p0, src1);
                float x1 = __shfl_sync(0xffffffffu, p1, src1);
                float y0 = __shfl_sync(0xffffffffu, p0, src2);
                float y1 = __shfl_sync(0xffffffffu, p1, src2);
                pa[0] = f2tf32((tg & 1) ? x1 : x0);
                pa[2] = f2tf32((tg & 1) ? y1 : y0);
                float x2 = __shfl_sync(0xffffffffu, p2, src1);
                float x3 = __shfl_sync(0xffffffffu, p3, src1);
                float y2 = __shfl_sync(0xffffffffu, p2, src2);
                float y3 = __shfl_sync(0xffffffffu, p3, src2);
                pa[1] = f2tf32((tg & 1) ? x3 : x2);
                pa[3] = f2tf32((tg & 1) ? y3 : y2);
            }
            int kk = wn * 32 + nn * 8;
            unsigned bv[8][2];
            #pragma unroll
            for (int p = 0; p < 4; p++)
                ldsm_x4(bv[2 * p][0], bv[2 * p][1], bv[2 * p + 1][0], bv[2 * p + 1][1],
                        VsB + ((p * 16 + b_nr) * VPITCH + kk + b_koff) * 4);
            #pragma unroll
            for (int dt = 0; dt < 8; dt++)
                mma_tf32(O[dt][0], O[dt][1], O[dt][2], O[dt][3],
                         pa[0], pa[1], pa[2], pa[3], bv[dt][0], bv[dt][1]);
        }
    }

    // accumulate partial O into g_att (zeroed; 2 wn x 2 splits adders)
    #pragma unroll
    for (int dt = 0; dt < 8; dt++) {
        int d0 = dt * 8 + 2 * tg;
        int r0 = i0 + wm * 16 + g;
        red_add_v2(&g_att[(size_t)(b * SS + r0) * DDIM + h * HDIM + d0],
                   O[dt][0], O[dt][1]);
        red_add_v2(&g_att[(size_t)(b * SS + r0 + 8) * DDIM + h * HDIM + d0],
                   O[dt][2], O[dt][3]);
    }
}

// ---------------- launch -----------------------------------------------------
extern "C" void kernel_launch(void* const* d_in, const int* in_sizes, int n_in,
                              void* d_out, int out_size) {
    const float* query = (const float*)d_in[0];
    const float* key   = (const float*)d_in[1];
    const float* value = (const float*)d_in[2];
    const float* Wq = (const float*)d_in[3];
    const float* bq = (const float*)d_in[4];
    const float* Wk = (const float*)d_in[5];
    const float* bk = (const float*)d_in[6];
    const float* Wv = (const float*)d_in[7];
    const float* bv = (const float*)d_in[8];
    const float* Wo = (const float*)d_in[9];
    const float* bo = (const float*)d_in[10];
    const float* qmapW = (const float*)d_in[11];
    const float* qmapb = (const float*)d_in[12];
    const float* qw    = (const float*)d_in[13];
    const float* ph    = (const float*)d_in[14];
    const float* es    = (const float*)d_in[15];

    float* out  = (float*)d_out;
    float* out2 = out + (size_t)MM * DDIM;

    {
        int n = MM * DDIM / 4;   // max of the two zero ranges
        zero_kernel<<<(n + 255) / 256, 256>>>(out2);
    }
    proj_kernel<<<dim3(DDIM / 128, MM / 128, 3), 256>>>(query, key, value,
                                                        Wq, bq, Wk, bk, Wv, bv);
    {
        int nrows = 2 * BHn * SS;
        qfeat_kernel<<<nrows / 8, 256>>>(qmapW, qmapb, qw, ph, es);
    }
    {
        size_t smemA = (size_t)(128 + 64) * QKPITCH * 4 + (size_t)ENTA * 4;  // 68092
        cudaFuncSetAttribute(attnA_kernel,
                             cudaFuncAttributeMaxDynamicSharedMemorySize, (int)smemA);
        attnA_kernel<<<dim3(SS / 128, BHn, 2), 256, smemA>>>(es);
    }
    {
        size_t smemB = (size_t)(64 + 64) * QKPITCH * 4 + (size_t)64 * VPITCH * 4
                     + (size_t)ENTB * 4;                                     // 63740
        cudaFuncSetAttribute(attnB_kernel,
                             cudaFuncAttributeMaxDynamicSharedMemorySize, (int)smemB);
        attnB_kernel<<<dim3(SS / 64, BHn, 2), 256, smemB>>>(es, out2);
    }
    outproj_kernel<<<dim3(DDIM / 128, MM / 128), 256>>>(Wo, bo, out);
}

// round 12
// speedup vs baseline: 1.1217x; 1.1139x over previous
#include <cuda_runtime.h>
#include <math.h>

#define BB   2
#define SS   768
#define DDIM 1024
#define HH   16
#define HDIM 64
#define NQh  8
#define NF   16
#define BHn  (BB*HH)     // 32
#define MM   (BB*SS)     // 1536
#define PROW 772         // 772 % 32 == 4 -> conflict-free ldmatrix rows
#define SPITCH 20
#define KPITCH 84        // 84 % 32 == 20 -> conflict-free
#define VPITCH 68        // 68 % 32 == 4  -> conflict-free
#define ENTN 831
#define ATHREADS 512

// ---------------- scratch ----------------------------------------------------
__device__ float g_Q[BHn*SS*HDIM];      // [bh][s][d]
__device__ float g_K[BHn*SS*HDIM];      // [bh][s][d]
__device__ float g_V[BHn*SS*HDIM];      // [bh][d][s]  (TRANSPOSED)
__device__ float g_fQ[BHn*SS*NF];
__device__ float g_fK[BHn*SS*NF];
__device__ float g_att[MM*DDIM];

// ---------------- helpers ----------------------------------------------------
__device__ __forceinline__ unsigned f2tf32(float f) {
    unsigned u;
    asm("cvt.rna.tf32.f32 %0, %1;" : "=r"(u) : "f"(f));
    return u;
}

__device__ __forceinline__ void mma_tf32(float& c0, float& c1, float& c2, float& c3,
                                         unsigned a0, unsigned a1, unsigned a2, unsigned a3,
                                         unsigned b0, unsigned b1) {
    asm volatile("mma.sync.aligned.m16n8k8.row.col.f32.tf32.tf32.f32 "
                 "{%0,%1,%2,%3}, {%4,%5,%6,%7}, {%8,%9}, {%0,%1,%2,%3};\n"
                 : "+f"(c0), "+f"(c1), "+f"(c2), "+f"(c3)
                 : "r"(a0), "r"(a1), "r"(a2), "r"(a3), "r"(b0), "r"(b1));
}

__device__ __forceinline__ void ldsm_x4(unsigned& r0, unsigned& r1,
                                        unsigned& r2, unsigned& r3, unsigned addr) {
    asm volatile("ldmatrix.sync.aligned.m8n8.x4.shared.b16 {%0,%1,%2,%3}, [%4];"
                 : "=r"(r0), "=r"(r1), "=r"(r2), "=r"(r3) : "r"(addr));
}

__device__ __forceinline__ void red_add_v4(float* p, float x, float y, float z, float w) {
    asm volatile("red.global.add.v4.f32 [%0], {%1,%2,%3,%4};"
                 :: "l"(p), "f"(x), "f"(y), "f"(z), "f"(w) : "memory");
}

// ============================================================================
// tf32 GEMM core for proj/outproj (256 threads, 128x128 tile)
// ============================================================================
#define GEMM_BODY(LOAD_A0, LOAD_A1, LOAD_B, NCHUNK)                              \
    float acc[4][4][4] = {};                                                     \
    int tid = threadIdx.x;                                                       \
    int wid = tid >> 5, lane = tid & 31;                                         \
    int wm = wid & 1, wnw = wid >> 1;                                            \
    int ar = tid >> 2, ac = (tid & 3) * 4;                                       \
    int bn = tid & 127, bk0 = (tid >> 7) * 8;                                    \
    int a_row = lane & 15, a_koff = (lane >> 4) * 4;                             \
    int b_nr  = (lane & 7) + ((lane >> 4) << 3);                                 \
    int b_koff = ((lane >> 3) & 1) * 4;                                          \
    unsigned aBase0 = (unsigned)__cvta_generic_to_shared(As0);                   \
    unsigned aBase1 = (unsigned)__cvta_generic_to_shared(As1);                   \
    unsigned bBase0 = (unsigned)__cvta_generic_to_shared(Bs0);                   \
    unsigned bBase1 = (unsigned)__cvta_generic_to_shared(Bs1);                   \
    float4 pa0, pa1; float pb[8];                                                \
    { int kg = 0;                                                                \
      pa0 = LOAD_A0(kg); pa1 = LOAD_A1(kg);                                      \
      _Pragma("unroll") for (int j = 0; j < 8; j++) pb[j] = LOAD_B(kg, j); }     \
    { unsigned* As = As0; unsigned* Bs = Bs0;                                    \
      *(uint4*)&As[ar * SPITCH + ac] =                                           \
          make_uint4(f2tf32(pa0.x), f2tf32(pa0.y), f2tf32(pa0.z), f2tf32(pa0.w));\
      *(uint4*)&As[(ar + 64) * SPITCH + ac] =                                    \
          make_uint4(f2tf32(pa1.x), f2tf32(pa1.y), f2tf32(pa1.z), f2tf32(pa1.w));\
      *(uint4*)&Bs[bn * SPITCH + bk0] =                                          \
          make_uint4(f2tf32(pb[0]), f2tf32(pb[1]), f2tf32(pb[2]), f2tf32(pb[3]));\
      *(uint4*)&Bs[bn * SPITCH + bk0 + 4] =                                      \
          make_uint4(f2tf32(pb[4]), f2tf32(pb[5]), f2tf32(pb[6]), f2tf32(pb[7]));}\
    __syncthreads();                                                             \
    for (int ch = 0; ch < (NCHUNK); ch++) {                                      \
        int buf = ch & 1;                                                        \
        if (ch + 1 < (NCHUNK)) {                                                 \
            int kg = (ch + 1) * 16;                                              \
            pa0 = LOAD_A0(kg); pa1 = LOAD_A1(kg);                                \
            _Pragma("unroll") for (int j = 0; j < 8; j++) pb[j] = LOAD_B(kg, j); \
        }                                                                        \
        unsigned aB = buf ? aBase1 : aBase0;                                     \
        unsigned bB = buf ? bBase1 : bBase0;                                     \
        _Pragma("unroll")                                                        \
        for (int ks = 0; ks < 2; ks++) {                                         \
            int kc = ks * 8;                                                     \
            unsigned af[4][4];                                                   \
            _Pragma("unroll")                                                    \
            for (int mt = 0; mt < 4; mt++)                                       \
                ldsm_x4(af[mt][0], af[mt][1], af[mt][2], af[mt][3],              \
                    aB + ((wm * 64 + mt * 16 + a_row) * SPITCH + kc + a_koff) * 4);\
            unsigned bf[4][2];                                                   \
            _Pragma("unroll")                                                    \
            for (int p = 0; p < 2; p++)                                          \
                ldsm_x4(bf[2 * p][0], bf[2 * p][1], bf[2 * p + 1][0],            \
                        bf[2 * p + 1][1],                                        \
                    bB + ((wnw * 32 + p * 16 + b_nr) * SPITCH + kc + b_koff) * 4);\
            _Pragma("unroll")                                                    \
            for (int mt = 0; mt < 4; mt++)                                       \
                _Pragma("unroll")                                                \
                for (int nt = 0; nt < 4; nt++)                                   \
                    mma_tf32(acc[mt][nt][0], acc[mt][nt][1],                     \
                             acc[mt][nt][2], acc[mt][nt][3],                     \
                             af[mt][0], af[mt][1], af[mt][2], af[mt][3],         \
                             bf[nt][0], bf[nt][1]);                              \
        }                                                                        \
        if (ch + 1 < (NCHUNK)) {                                                 \
            unsigned* As = buf ? As0 : As1;                                      \
            unsigned* Bs = buf ? Bs0 : Bs1;                                      \
            *(uint4*)&As[ar * SPITCH + ac] =                                     \
                make_uint4(f2tf32(pa0.x), f2tf32(pa0.y), f2tf32(pa0.z), f2tf32(pa0.w));\
            *(uint4*)&As[(ar + 64) * SPITCH + ac] =                              \
                make_uint4(f2tf32(pa1.x), f2tf32(pa1.y), f2tf32(pa1.z), f2tf32(pa1.w));\
            *(uint4*)&Bs[bn * SPITCH + bk0] =                                    \
                make_uint4(f2tf32(pb[0]), f2tf32(pb[1]), f2tf32(pb[2]), f2tf32(pb[3]));\
            *(uint4*)&Bs[bn * SPITCH + bk0 + 4] =                                \
                make_uint4(f2tf32(pb[4]), f2tf32(pb[5]), f2tf32(pb[6]), f2tf32(pb[7]));\
        }                                                                        \
        __syncthreads();                                                         \
    }

// ---------------- fused QKV projection (2 CTAs/SM) ---------------------------
__global__ __launch_bounds__(256, 2) void proj_kernel(
        const float* __restrict__ q, const float* __restrict__ k,
        const float* __restrict__ v,
        const float* __restrict__ Wq, const float* __restrict__ bq,
        const float* __restrict__ Wk, const float* __restrict__ bk,
        const float* __restrict__ Wv, const float* __restrict__ bv) {
    int which = blockIdx.z;
    const float* A    = (which == 0) ? q  : (which == 1) ? k  : v;
    const float* W    = (which == 0) ? Wq : (which == 1) ? Wk : Wv;
    const float* bias = (which == 0) ? bq : (which == 1) ? bk : bv;
    float*       out  = (which == 0) ? g_Q : (which == 1) ? g_K : g_V;

    __shared__ unsigned As0[128 * SPITCH], As1[128 * SPITCH];
    __shared__ unsigned Bs0[128 * SPITCH], Bs1[128 * SPITCH];
    int row0 = blockIdx.y * 128, col0 = blockIdx.x * 128;

#define LA0(kg) (*(const float4*)&A[(size_t)(row0 + ar) * DDIM + (kg) + ac])
#define LA1(kg) (*(const float4*)&A[(size_t)(row0 + 64 + ar) * DDIM + (kg) + ac])
#define LB(kg, j) (W[(size_t)((kg) + bk0 + (j)) * DDIM + col0 + bn])
    GEMM_BODY(LA0, LA1, LB, DDIM / 16)
#undef LA0
#undef LA1
#undef LB

    int g = lane >> 2, tg = lane & 3;
    #pragma unroll
    for (int mt = 0; mt < 4; mt++)
        #pragma unroll
        for (int nt = 0; nt < 4; nt++) {
            int gm = row0 + wm * 64 + mt * 16 + g;
            int gn = col0 + wnw * 32 + nt * 8 + tg * 2;
            #pragma unroll
            for (int hrow = 0; hrow < 2; hrow++) {
                int m = gm + hrow * 8;
                int b = m / SS, s = m % SS;
                int h = gn >> 6, d = gn & 63;
                if (which == 2) {   // V transposed: [bh][d][s]
                    #pragma unroll
                    for (int j = 0; j < 2; j++)
                        out[((size_t)(b * HH + h) * HDIM + d + j) * SS + s] =
                            acc[mt][nt][hrow * 2 + j] + bias[gn + j];
                } else {            // Q/K: [bh][s][d]
                    float2 st;
                    st.x = acc[mt][nt][hrow * 2]     + bias[gn];
                    st.y = acc[mt][nt][hrow * 2 + 1] + bias[gn + 1];
                    *(float2*)&out[((size_t)(b * HH + h) * SS + s) * HDIM + d] = st;
                }
            }
        }
}

// ---------------- out = attended @ Wo + bo (2 CTAs/SM) -----------------------
__global__ __launch_bounds__(256, 2) void outproj_kernel(const float* __restrict__ Wo,
                                                         const float* __restrict__ bo,
                                                         float* __restrict__ out) {
    __shared__ unsigned As0[128 * SPITCH], As1[128 * SPITCH];
    __shared__ unsigned Bs0[128 * SPITCH], Bs1[128 * SPITCH];
    int row0 = blockIdx.y * 128, col0 = blockIdx.x * 128;

#define LA0(kg) (*(const float4*)&g_att[(size_t)(row0 + ar) * DDIM + (kg) + ac])
#define LA1(kg) (*(const float4*)&g_att[(size_t)(row0 + 64 + ar) * DDIM + (kg) + ac])
#define LB(kg, j) (Wo[(size_t)((kg) + bk0 + (j)) * DDIM + col0 + bn])
    GEMM_BODY(LA0, LA1, LB, DDIM / 16)
#undef LA0
#undef LA1
#undef LB

    int g = lane >> 2, tg = lane & 3;
    #pragma unroll
    for (int mt = 0; mt < 4; mt++)
        #pragma unroll
        for (int nt = 0; nt < 4; nt++) {
            int gm = row0 + wm * 64 + mt * 16 + g;
            int gn = col0 + wnw * 32 + nt * 8 + tg * 2;
            #pragma unroll
            for (int hrow = 0; hrow < 2; hrow++) {
                int m = gm + hrow * 8;
                float2 st;
                st.x = acc[mt][nt][hrow * 2]     + bo[gn];
                st.y = acc[mt][nt][hrow * 2 + 1] + bo[gn + 1];
                *(float2*)&out[(size_t)m * DDIM + gn] = st;
            }
        }
}

// ---------------- quantum features (warp-per-row) ---------------------------
__global__ __launch_bounds__(256) void qfeat_kernel(
        const float* __restrict__ qmapW, const float* __restrict__ qmapb,
        const float* __restrict__ qw, const float* __restrict__ ph,
        const float* __restrict__ es_ptr) {
    int gw   = (blockIdx.x * blockDim.x + threadIdx.x) >> 5;
    int lane = threadIdx.x & 31;
    if (gw >= 2 * BHn * SS) return;
    int side = gw / (BHn * SS);
    int r    = gw % (BHn * SS);
    int h    = (r / SS) % HH;
    const float* row = ((side == 0) ? g_Q : g_K) + (size_t)r * HDIM;
    float rv0 = row[lane], rv1 = row[lane + 32];

    float mydot = 0.f;
    #pragma unroll
    for (int n = 0; n < NQh; n++) {
        float p = rv0 * qmapW[lane * NQh + n] + rv1 * qmapW[(lane + 32) * NQh + n];
        #pragma unroll
        for (int o = 16; o; o >>= 1) p += __shfl_xor_sync(0xffffffffu, p, o);
        if (lane == n) mydot = p;
    }
    if (lane < NQh) {
        float a = tanhf(mydot + qmapb[lane]);
        float s, c;
        if (side == 0) {
            float mix = 1.f / (1.f + __expf(-*es_ptr));
            float w = (1.f / (1.f + __expf(-qw[h * NQh + lane]))) * (1.0f / NQh) * mix;
            sincosf(a + ph[h * NQh + lane], &s, &c);
            g_fQ[(size_t)r * NF + lane]       = w * c;
            g_fQ[(size_t)r * NF + NQh + lane] = w * s;
        } else {
            sincosf(a, &s, &c);
            g_fK[(size_t)r * NF + lane]       = c;
            g_fK[(size_t)r * NF + NQh + lane] = s;
        }
    }
}

// ---------------- zero out2 --------------------------------------------------
__global__ void zero_out2_kernel(float* __restrict__ out2) {
    int idx = blockIdx.x * blockDim.x + threadIdx.x;
    if (idx < BB * SS * SS / 4)
        ((float4*)out2)[idx] = make_float4(0.f, 0.f, 0.f, 0.f);
}

// ---------------- fused attention (512 threads, 16 warps: 4m x 4n) ----------
__global__ __launch_bounds__(ATHREADS) void attn_kernel(const float* __restrict__ es_ptr,
                                                        float* __restrict__ out2) {
    extern __shared__ float P[];                       // [64][PROW]
    unsigned* Ks   = (unsigned*)(P + 64 * PROW);       // phase 1
    float*    entT = (float*)(Ks + 64 * KPITCH);       // phase 1 LUT
    unsigned* Vs0  = (unsigned*)(P + 64 * PROW);       // phase 3
    unsigned* Vs1  = Vs0 + 64 * VPITCH;

    int bh = blockIdx.y;
    int b = bh >> 4, h = bh & 15;
    int i0 = blockIdx.x * 64;
    const float* Qp  = g_Q  + (size_t)bh * SS * HDIM;
    const float* Kp  = g_K  + (size_t)bh * SS * HDIM;
    const float* Vtp = g_V  + (size_t)bh * HDIM * SS;  // [d][s]
    const float* Fqp = g_fQ + (size_t)bh * SS * NF;
    const float* Fkp = g_fK + (size_t)bh * SS * NF;
    float* o2p = out2 + (size_t)b * SS * SS;

    int tid = threadIdx.x;
    int wid = tid >> 5, lane = tid & 31;
    int wm = wid & 3, wn = wid >> 2;                   // 4m x 4n
    int g = lane >> 2, tg = lane & 3;
    int a_row = lane & 15, a_koff = (lane >> 4) * 4;
    int b_nr  = (lane & 7) + ((lane >> 4) << 3);
    int b_koff = ((lane >> 3) & 1) * 4;
    unsigned PBase   = (unsigned)__cvta_generic_to_shared(P);
    unsigned KsBase  = (unsigned)__cvta_generic_to_shared(Ks);
    unsigned VsBase0 = (unsigned)__cvta_generic_to_shared(Vs0);
    unsigned VsBase1 = (unsigned)__cvta_generic_to_shared(Vs1);

    float es  = *es_ptr;
    float mix = 1.f / (1.f + __expf(-es));
    float ca  = (1.f - mix) * 0.125f;

    for (int t = tid; t < ENTN; t += ATHREADS)
        entT[t] = __expf(-0.1f * fabsf((float)(i0 - 767 + t)));

    // ---- stage Q(*ca)+Fq into Ks, preload persistent a-fragments -----------
    {
        #pragma unroll
        for (int it = 0; it < 2; it++) {
            int fid = tid + ATHREADS * it;
            int r = fid >> 4, c4 = (fid & 15) * 4;
            float4 f = *(const float4*)&Qp[(size_t)(i0 + r) * HDIM + c4];
            *(uint4*)&Ks[r * KPITCH + c4] =
                make_uint4(f2tf32(ca * f.x), f2tf32(ca * f.y),
                           f2tf32(ca * f.z), f2tf32(ca * f.w));
        }
        if (tid < 256) {
            int r = tid >> 2, c4 = (tid & 3) * 4;
            float4 f = *(const float4*)&Fqp[(size_t)(i0 + r) * NF + c4];
            *(uint4*)&Ks[r * KPITCH + 64 + c4] =
                make_uint4(f2tf32(f.x), f2tf32(f.y), f2tf32(f.z), f2tf32(f.w));
        }
    }
    __syncthreads();
    unsigned afr[10][4];
    #pragma unroll
    for (int s = 0; s < 10; s++) {
        int r = wm * 16 + g, c = s * 8 + tg;
        afr[s][0] = Ks[r * KPITCH + c];
        afr[s][1] = Ks[(r + 8) * KPITCH + c];
        afr[s][2] = Ks[r * KPITCH + c + 4];
        afr[s][3] = Ks[(r + 8) * KPITCH + c + 4];
    }
    __syncthreads();

    // ---- phase 1: scores over 12 K-chunks (reg-prefetched) -----------------
    float4 rc[2], rq;
    {
        #pragma unroll
        for (int it = 0; it < 2; it++) {
            int fid = tid + ATHREADS * it;
            int r = fid >> 4, c4 = (fid & 15) * 4;
            rc[it] = *(const float4*)&Kp[(size_t)r * HDIM + c4];
        }
        if (tid < 256) {
            int r = tid >> 2, c4 = (tid & 3) * 4;
            rq = *(const float4*)&Fkp[(size_t)r * NF + c4];
        }
        #pragma unroll
        for (int it = 0; it < 2; it++) {
            int fid = tid + ATHREADS * it;
            int r = fid >> 4, c4 = (fid & 15) * 4;
            *(uint4*)&Ks[r * KPITCH + c4] =
                make_uint4(f2tf32(rc[it].x), f2tf32(rc[it].y),
                           f2tf32(rc[it].z), f2tf32(rc[it].w));
        }
        if (tid < 256) {
            int r = tid >> 2, c4 = (tid & 3) * 4;
            *(uint4*)&Ks[r * KPITCH + 64 + c4] =
                make_uint4(f2tf32(rq.x), f2tf32(rq.y), f2tf32(rq.z), f2tf32(rq.w));
        }
        __syncthreads();
    }
    for (int jc = 0; jc < 12; jc++) {
        int j0 = jc * 64;
        if (jc + 1 < 12) {
            int jn = j0 + 64;
            #pragma unroll
            for (int it = 0; it < 2; it++) {
                int fid = tid + ATHREADS * it;
                int r = fid >> 4, c4 = (fid & 15) * 4;
                rc[it] = *(const float4*)&Kp[(size_t)(jn + r) * HDIM + c4];
            }
            if (tid < 256) {
                int r = tid >> 2, c4 = (tid & 3) * 4;
                rq = *(const float4*)&Fkp[(size_t)(jn + r) * NF + c4];
            }
        }
        float accC[2][4] = {}, accQ[2][4] = {};
        #pragma unroll
        for (int s = 0; s < 10; s++) {
            int kc = s * 8;
            unsigned bf[2][2];
            ldsm_x4(bf[0][0], bf[0][1], bf[1][0], bf[1][1],
                    KsBase + ((wn * 16 + b_nr) * KPITCH + kc + b_koff) * 4);
            #pragma unroll
            for (int nt = 0; nt < 2; nt++) {
                if (s < 8)
                    mma_tf32(accC[nt][0], accC[nt][1], accC[nt][2], accC[nt][3],
                             afr[s][0], afr[s][1], afr[s][2], afr[s][3],
                             bf[nt][0], bf[nt][1]);
                else
                    mma_tf32(accQ[nt][0], accQ[nt][1], accQ[nt][2], accQ[nt][3],
                             afr[s][0], afr[s][1], afr[s][2], afr[s][3],
                             bf[nt][0], bf[nt][1]);
            }
        }
        #pragma unroll
        for (int nt = 0; nt < 2; nt++) {
            int r  = wm * 16 + g;
            int cl = wn * 16 + nt * 8 + tg * 2;
            #pragma unroll
            for (int hrow = 0; hrow < 2; hrow++) {
                int rr = r + hrow * 8;
                int base = rr + 767 - j0 - cl;
                float e0 = entT[base];
                float e1 = entT[base - 1];
                float2 st;
                st.x = accC[nt][hrow * 2]     + e0 * accQ[nt][hrow * 2];
                st.y = accC[nt][hrow * 2 + 1] + e1 * accQ[nt][hrow * 2 + 1];
                *(float2*)&P[rr * PROW + j0 + cl] = st;
            }
        }
        __syncthreads();
        if (jc + 1 < 12) {
            #pragma unroll
            for (int it = 0; it < 2; it++) {
                int fid = tid + ATHREADS * it;
                int r = fid >> 4, c4 = (fid & 15) * 4;
                *(uint4*)&Ks[r * KPITCH + c4] =
                    make_uint4(f2tf32(rc[it].x), f2tf32(rc[it].y),
                               f2tf32(rc[it].z), f2tf32(rc[it].w));
            }
            if (tid < 256) {
                int r = tid >> 2, c4 = (tid & 3) * 4;
                *(uint4*)&Ks[r * KPITCH + 64 + c4] =
                    make_uint4(f2tf32(rq.x), f2tf32(rq.y), f2tf32(rq.z), f2tf32(rq.w));
            }
        }
        __syncthreads();
    }

    // ---- phase 2: softmax + head-mean reduction into out2 (4 rows/warp) ----
    for (int rr = wid; rr < 64; rr += 16) {
        float4* row4 = (float4*)(P + rr * PROW);
        float4 v[6];
        float m = -1e30f;
        #pragma unroll
        for (int u = 0; u < 6; u++) {
            v[u] = row4[lane + u * 32];
            m = fmaxf(m, fmaxf(fmaxf(v[u].x, v[u].y), fmaxf(v[u].z, v[u].w)));
        }
        #pragma unroll
        for (int o = 16; o; o >>= 1) m = fmaxf(m, __shfl_xor_sync(0xffffffffu, m, o));
        float ssum = 0.f;
        #pragma unroll
        for (int u = 0; u < 6; u++) {
            v[u].x = __expf(v[u].x - m); v[u].y = __expf(v[u].y - m);
            v[u].z = __expf(v[u].z - m); v[u].w = __expf(v[u].w - m);
            ssum += (v[u].x + v[u].y) + (v[u].z + v[u].w);
        }
        #pragma unroll
        for (int o = 16; o; o >>= 1) ssum += __shfl_xor_sync(0xffffffffu, ssum, o);
        float inv = __frcp_rn(ssum);
        float* o2row = o2p + (size_t)(i0 + rr) * SS;
        #pragma unroll
        for (int u = 0; u < 6; u++) {
            float4 t;
            t.x = __uint_as_float(f2tf32(v[u].x * inv));
            t.y = __uint_as_float(f2tf32(v[u].y * inv));
            t.z = __uint_as_float(f2tf32(v[u].z * inv));
            t.w = __uint_as_float(f2tf32(v[u].w * inv));
            row4[lane + u * 32] = t;
            red_add_v4(o2row + (lane + u * 32) * 4,
                       t.x * (1.0f / HH), t.y * (1.0f / HH),
                       t.z * (1.0f / HH), t.w * (1.0f / HH));
        }
    }

    // ---- phase 3: AV via ldmatrix on P and double-buffered Vs --------------
    float acc[2][4] = {};
    float4 vreg[2];
    {
        #pragma unroll
        for (int it = 0; it < 2; it++) {
            int fid = tid + ATHREADS * it;
            int d = fid >> 4, c4 = (fid & 15) * 4;
            vreg[it] = *(const float4*)&Vtp[(size_t)d * SS + c4];
        }
        __syncthreads();
        #pragma unroll
        for (int it = 0; it < 2; it++) {
            int fid = tid + ATHREADS * it;
            int d = fid >> 4, c4 = (fid & 15) * 4;
            *(uint4*)&Vs0[d * VPITCH + c4] =
                make_uint4(f2tf32(vreg[it].x), f2tf32(vreg[it].y),
                           f2tf32(vreg[it].z), f2tf32(vreg[it].w));
        }
        __syncthreads();
    }
    for (int c = 0; c < 12; c++) {
        int k0 = c * 64;
        unsigned curB = (c & 1) ? VsBase1 : VsBase0;
        unsigned* nxt = (c & 1) ? Vs0 : Vs1;
        if (c + 1 < 12) {
            int kn = k0 + 64;
            #pragma unroll
            for (int it = 0; it < 2; it++) {
                int fid = tid + ATHREADS * it;
                int d = fid >> 4, c4 = (fid & 15) * 4;
                vreg[it] = *(const float4*)&Vtp[(size_t)d * SS + kn + c4];
            }
        }
        #pragma unroll
        for (int s = 0; s < 8; s++) {
            int kc = s * 8;
            unsigned af[4];
            ldsm_x4(af[0], af[1], af[2], af[3],
                    PBase + ((wm * 16 + a_row) * PROW + k0 + kc + a_koff) * 4);
            unsigned bf[2][2];
            ldsm_x4(bf[0][0], bf[0][1], bf[1][0], bf[1][1],
                    curB + ((wn * 16 + b_nr) * VPITCH + kc + b_koff) * 4);
            #pragma unroll
            for (int nt = 0; nt < 2; nt++)
                mma_tf32(acc[nt][0], acc[nt][1], acc[nt][2], acc[nt][3],
                         af[0], af[1], af[2], af[3], bf[nt][0], bf[nt][1]);
        }
        if (c + 1 < 12) {
            #pragma unroll
            for (int it = 0; it < 2; it++) {
                int fid = tid + ATHREADS * it;
                int d = fid >> 4, c4 = (fid & 15) * 4;
                *(uint4*)&nxt[d * VPITCH + c4] =
                    make_uint4(f2tf32(vreg[it].x), f2tf32(vreg[it].y),
                               f2tf32(vreg[it].z), f2tf32(vreg[it].w));
            }
        }
        __syncthreads();
    }
    #pragma unroll
    for (int nt = 0; nt < 2; nt++) {
        int r = wm * 16 + g;
        int d0 = wn * 16 + nt * 8 + tg * 2;
        #pragma unroll
        for (int hrow = 0; hrow < 2; hrow++) {
            int s_ = i0 + r + hrow * 8;
            *(float2*)&g_att[(size_t)(b * SS + s_) * DDIM + h * HDIM + d0] =
                make_float2(acc[nt][hrow * 2], acc[nt][hrow * 2 + 1]);
        }
    }
}

// ---------------- launch -----------------------------------------------------
extern "C" void kernel_launch(void* const* d_in, const int* in_sizes, int n_in,
                              void* d_out, int out_size) {
    const float* query = (const float*)d_in[0];
    const float* key   = (const float*)d_in[1];
    const float* value = (const float*)d_in[2];
    const float* Wq = (const float*)d_in[3];
    const float* bq = (const float*)d_in[4];
    const float* Wk = (const float*)d_in[5];
    const float* bk = (const float*)d_in[6];
    const float* Wv = (const float*)d_in[7];
    const float* bv = (const float*)d_in[8];
    const float* Wo = (const float*)d_in[9];
    const float* bo = (const float*)d_in[10];
    const float* qmapW = (const float*)d_in[11];
    const float* qmapb = (const float*)d_in[12];
    const float* qw    = (const float*)d_in[13];
    const float* ph    = (const float*)d_in[14];
    const float* es    = (const float*)d_in[15];

    float* out  = (float*)d_out;
    float* out2 = out + (size_t)MM * DDIM;

    {
        int n = BB * SS * SS / 4;
        zero_out2_kernel<<<(n + 255) / 256, 256>>>(out2);
    }
    proj_kernel<<<dim3(DDIM / 128, MM / 128, 3), 256>>>(query, key, value,
                                                        Wq, bq, Wk, bk, Wv, bv);
    {
        int nrows = 2 * BHn * SS;
        qfeat_kernel<<<nrows / 8, 256>>>(qmapW, qmapb, qw, ph, es);
    }
    {
        size_t smem = (size_t)64 * PROW * 4 + (size_t)2 * 64 * VPITCH * 4; // 232448
        cudaFuncSetAttribute(attn_kernel,
                             cudaFuncAttributeMaxDynamicSharedMemorySize, (int)smem);
        attn_kernel<<<dim3(SS / 64, BHn), ATHREADS, smem>>>(es, out2);
    }
    outproj_kernel<<<dim3(DDIM / 128, MM / 128), 256>>>(Wo, bo, out);
}

// round 13
// speedup vs baseline: 1.1222x; 1.0005x over previous
#include <cuda_runtime.h>
#include <math.h>

#define BB   2
#define SS   768
#define DDIM 1024
#define HH   16
#define HDIM 64
#define NQh  8
#define NF   16
#define BHn  (BB*HH)     // 32
#define MM   (BB*SS)     // 1536
#define PROW 772         // 772 % 32 == 4 -> conflict-free ldmatrix rows
#define SPITCH 20
#define KPITCH 84        // 84 % 32 == 20 -> conflict-free
#define VPITCH 68        // 68 % 32 == 4  -> conflict-free
#define ENTN 831
#define ATHREADS 512

// ---------------- scratch ----------------------------------------------------
__device__ float g_Q[BHn*SS*HDIM];      // [bh][s][d]
__device__ float g_K[BHn*SS*HDIM];      // [bh][s][d]
__device__ float g_V[BHn*SS*HDIM];      // [bh][d][s]  (TRANSPOSED)
__device__ float g_fQ[BHn*SS*NF];
__device__ float g_fK[BHn*SS*NF];
__device__ float g_att[MM*DDIM];

// ---------------- helpers ----------------------------------------------------
__device__ __forceinline__ unsigned f2tf32(float f) {
    unsigned u;
    asm("cvt.rna.tf32.f32 %0, %1;" : "=r"(u) : "f"(f));
    return u;
}

__device__ __forceinline__ void mma_tf32(float& c0, float& c1, float& c2, float& c3,
                                         unsigned a0, unsigned a1, unsigned a2, unsigned a3,
                                         unsigned b0, unsigned b1) {
    asm volatile("mma.sync.aligned.m16n8k8.row.col.f32.tf32.tf32.f32 "
                 "{%0,%1,%2,%3}, {%4,%5,%6,%7}, {%8,%9}, {%0,%1,%2,%3};\n"
                 : "+f"(c0), "+f"(c1), "+f"(c2), "+f"(c3)
                 : "r"(a0), "r"(a1), "r"(a2), "r"(a3), "r"(b0), "r"(b1));
}

__device__ __forceinline__ void ldsm_x4(unsigned& r0, unsigned& r1,
                                        unsigned& r2, unsigned& r3, unsigned addr) {
    asm volatile("ldmatrix.sync.aligned.m8n8.x4.shared.b16 {%0,%1,%2,%3}, [%4];"
                 : "=r"(r0), "=r"(r1), "=r"(r2), "=r"(r3) : "r"(addr));
}

__device__ __forceinline__ void red_add_v4(float* p, float x, float y, float z, float w) {
    asm volatile("red.global.add.v4.f32 [%0], {%1,%2,%3,%4};"
                 :: "l"(p), "f"(x), "f"(y), "f"(z), "f"(w) : "memory");
}

// ============================================================================
// tf32 GEMM core for proj/outproj (256 threads, 128x128 tile)
// ============================================================================
#define GEMM_BODY(LOAD_A0, LOAD_A1, LOAD_B, NCHUNK)                              \
    float acc[4][4][4] = {};                                                     \
    int tid = threadIdx.x;                                                       \
    int wid = tid >> 5, lane = tid & 31;                                         \
    int wm = wid & 1, wnw = wid >> 1;                                            \
    int ar = tid >> 2, ac = (tid & 3) * 4;                                       \
    int bn = tid & 127, bk0 = (tid >> 7) * 8;                                    \
    int a_row = lane & 15, a_koff = (lane >> 4) * 4;                             \
    int b_nr  = (lane & 7) + ((lane >> 4) << 3);                                 \
    int b_koff = ((lane >> 3) & 1) * 4;                                          \
    unsigned aBase0 = (unsigned)__cvta_generic_to_shared(As0);                   \
    unsigned aBase1 = (unsigned)__cvta_generic_to_shared(As1);                   \
    unsigned bBase0 = (unsigned)__cvta_generic_to_shared(Bs0);                   \
    unsigned bBase1 = (unsigned)__cvta_generic_to_shared(Bs1);                   \
    float4 pa0, pa1; float pb[8];                                                \
    { int kg = 0;                                                                \
      pa0 = LOAD_A0(kg); pa1 = LOAD_A1(kg);                                      \
      _Pragma("unroll") for (int j = 0; j < 8; j++) pb[j] = LOAD_B(kg, j); }     \
    { unsigned* As = As0; unsigned* Bs = Bs0;                                    \
      *(uint4*)&As[ar * SPITCH + ac] =                                           \
          make_uint4(f2tf32(pa0.x), f2tf32(pa0.y), f2tf32(pa0.z), f2tf32(pa0.w));\
      *(uint4*)&As[(ar + 64) * SPITCH + ac] =                                    \
          make_uint4(f2tf32(pa1.x), f2tf32(pa1.y), f2tf32(pa1.z), f2tf32(pa1.w));\
      *(uint4*)&Bs[bn * SPITCH + bk0] =                                          \
          make_uint4(f2tf32(pb[0]), f2tf32(pb[1]), f2tf32(pb[2]), f2tf32(pb[3]));\
      *(uint4*)&Bs[bn * SPITCH + bk0 + 4] =                                      \
          make_uint4(f2tf32(pb[4]), f2tf32(pb[5]), f2tf32(pb[6]), f2tf32(pb[7]));}\
    __syncthreads();                                                             \
    for (int ch = 0; ch < (NCHUNK); ch++) {                                      \
        int buf = ch & 1;                                                        \
        if (ch + 1 < (NCHUNK)) {                                                 \
            int kg = (ch + 1) * 16;                                              \
            pa0 = LOAD_A0(kg); pa1 = LOAD_A1(kg);                                \
            _Pragma("unroll") for (int j = 0; j < 8; j++) pb[j] = LOAD_B(kg, j); \
        }                                                                        \
        unsigned aB = buf ? aBase1 : aBase0;                                     \
        unsigned bB = buf ? bBase1 : bBase0;                                     \
        _Pragma("unroll")                                                        \
        for (int ks = 0; ks < 2; ks++) {                                         \
            int kc = ks * 8;                                                     \
            unsigned af[4][4];                                                   \
            _Pragma("unroll")                                                    \
            for (int mt = 0; mt < 4; mt++)                                       \
                ldsm_x4(af[mt][0], af[mt][1], af[mt][2], af[mt][3],              \
                    aB + ((wm * 64 + mt * 16 + a_row) * SPITCH + kc + a_koff) * 4);\
            unsigned bf[4][2];                                                   \
            _Pragma("unroll")                                                    \
            for (int p = 0; p < 2; p++)                                          \
                ldsm_x4(bf[2 * p][0], bf[2 * p][1], bf[2 * p + 1][0],            \
                        bf[2 * p + 1][1],                                        \
                    bB + ((wnw * 32 + p * 16 + b_nr) * SPITCH + kc + b_koff) * 4);\
            _Pragma("unroll")                                                    \
            for (int mt = 0; mt < 4; mt++)                                       \
                _Pragma("unroll")                                                \
                for (int nt = 0; nt < 4; nt++)                                   \
                    mma_tf32(acc[mt][nt][0], acc[mt][nt][1],                     \
                             acc[mt][nt][2], acc[mt][nt][3],                     \
                             af[mt][0], af[mt][1], af[mt][2], af[mt][3],         \
                             bf[nt][0], bf[nt][1]);                              \
        }                                                                        \
        if (ch + 1 < (NCHUNK)) {                                                 \
            unsigned* As = buf ? As0 : As1;                                      \
            unsigned* Bs = buf ? Bs0 : Bs1;                                      \
            *(uint4*)&As[ar * SPITCH + ac] =                                     \
                make_uint4(f2tf32(pa0.x), f2tf32(pa0.y), f2tf32(pa0.z), f2tf32(pa0.w));\
            *(uint4*)&As[(ar + 64) * SPITCH + ac] =                              \
                make_uint4(f2tf32(pa1.x), f2tf32(pa1.y), f2tf32(pa1.z), f2tf32(pa1.w));\
            *(uint4*)&Bs[bn * SPITCH + bk0] =                                    \
                make_uint4(f2tf32(pb[0]), f2tf32(pb[1]), f2tf32(pb[2]), f2tf32(pb[3]));\
            *(uint4*)&Bs[bn * SPITCH + bk0 + 4] =                                \
                make_uint4(f2tf32(pb[4]), f2tf32(pb[5]), f2tf32(pb[6]), f2tf32(pb[7]));\
        }                                                                        \
        __syncthreads();                                                         \
    }

// ---------------- fused QKV projection (2 CTAs/SM) ---------------------------
__global__ __launch_bounds__(256, 2) void proj_kernel(
        const float* __restrict__ q, const float* __restrict__ k,
        const float* __restrict__ v,
        const float* __restrict__ Wq, const float* __restrict__ bq,
        const float* __restrict__ Wk, const float* __restrict__ bk,
        const float* __restrict__ Wv, const float* __restrict__ bv) {
    int which = blockIdx.z;
    const float* A    = (which == 0) ? q  : (which == 1) ? k  : v;
    const float* W    = (which == 0) ? Wq : (which == 1) ? Wk : Wv;
    const float* bias = (which == 0) ? bq : (which == 1) ? bk : bv;
    float*       out  = (which == 0) ? g_Q : (which == 1) ? g_K : g_V;

    __shared__ unsigned As0[128 * SPITCH], As1[128 * SPITCH];
    __shared__ unsigned Bs0[128 * SPITCH], Bs1[128 * SPITCH];
    int row0 = blockIdx.y * 128, col0 = blockIdx.x * 128;

#define LA0(kg) (*(const float4*)&A[(size_t)(row0 + ar) * DDIM + (kg) + ac])
#define LA1(kg) (*(const float4*)&A[(size_t)(row0 + 64 + ar) * DDIM + (kg) + ac])
#define LB(kg, j) (W[(size_t)((kg) + bk0 + (j)) * DDIM + col0 + bn])
    GEMM_BODY(LA0, LA1, LB, DDIM / 16)
#undef LA0
#undef LA1
#undef LB

    int g = lane >> 2, tg = lane & 3;
    #pragma unroll
    for (int mt = 0; mt < 4; mt++)
        #pragma unroll
        for (int nt = 0; nt < 4; nt++) {
            int gm = row0 + wm * 64 + mt * 16 + g;
            int gn = col0 + wnw * 32 + nt * 8 + tg * 2;
            #pragma unroll
            for (int hrow = 0; hrow < 2; hrow++) {
                int m = gm + hrow * 8;
                int b = m / SS, s = m % SS;
                int h = gn >> 6, d = gn & 63;
                if (which == 2) {   // V transposed: [bh][d][s]
                    #pragma unroll
                    for (int j = 0; j < 2; j++)
                        out[((size_t)(b * HH + h) * HDIM + d + j) * SS + s] =
                            acc[mt][nt][hrow * 2 + j] + bias[gn + j];
                } else {            // Q/K: [bh][s][d]
                    float2 st;
                    st.x = acc[mt][nt][hrow * 2]     + bias[gn];
                    st.y = acc[mt][nt][hrow * 2 + 1] + bias[gn + 1];
                    *(float2*)&out[((size_t)(b * HH + h) * SS + s) * HDIM + d] = st;
                }
            }
        }
}

// ---------------- out = attended @ Wo + bo (2 CTAs/SM) -----------------------
__global__ __launch_bounds__(256, 2) void outproj_kernel(const float* __restrict__ Wo,
                                                         const float* __restrict__ bo,
                                                         float* __restrict__ out) {
    __shared__ unsigned As0[128 * SPITCH], As1[128 * SPITCH];
    __shared__ unsigned Bs0[128 * SPITCH], Bs1[128 * SPITCH];
    int row0 = blockIdx.y * 128, col0 = blockIdx.x * 128;

#define LA0(kg) (*(const float4*)&g_att[(size_t)(row0 + ar) * DDIM + (kg) + ac])
#define LA1(kg) (*(const float4*)&g_att[(size_t)(row0 + 64 + ar) * DDIM + (kg) + ac])
#define LB(kg, j) (Wo[(size_t)((kg) + bk0 + (j)) * DDIM + col0 + bn])
    GEMM_BODY(LA0, LA1, LB, DDIM / 16)
#undef LA0
#undef LA1
#undef LB

    int g = lane >> 2, tg = lane & 3;
    #pragma unroll
    for (int mt = 0; mt < 4; mt++)
        #pragma unroll
        for (int nt = 0; nt < 4; nt++) {
            int gm = row0 + wm * 64 + mt * 16 + g;
            int gn = col0 + wnw * 32 + nt * 8 + tg * 2;
            #pragma unroll
            for (int hrow = 0; hrow < 2; hrow++) {
                int m = gm + hrow * 8;
                float2 st;
                st.x = acc[mt][nt][hrow * 2]     + bo[gn];
                st.y = acc[mt][nt][hrow * 2 + 1] + bo[gn + 1];
                *(float2*)&out[(size_t)m * DDIM + gn] = st;
            }
        }
}

// ---------------- quantum features (warp-per-row) ---------------------------
__global__ __launch_bounds__(256) void qfeat_kernel(
        const float* __restrict__ qmapW, const float* __restrict__ qmapb,
        const float* __restrict__ qw, const float* __restrict__ ph,
        const float* __restrict__ es_ptr) {
    int gw   = (blockIdx.x * blockDim.x + threadIdx.x) >> 5;
    int lane = threadIdx.x & 31;
    if (gw >= 2 * BHn * SS) return;
    int side = gw / (BHn * SS);
    int r    = gw % (BHn * SS);
    int h    = (r / SS) % HH;
    const float* row = ((side == 0) ? g_Q : g_K) + (size_t)r * HDIM;
    float rv0 = row[lane], rv1 = row[lane + 32];

    float mydot = 0.f;
    #pragma unroll
    for (int n = 0; n < NQh; n++) {
        float p = rv0 * qmapW[lane * NQh + n] + rv1 * qmapW[(lane + 32) * NQh + n];
        #pragma unroll
        for (int o = 16; o; o >>= 1) p += __shfl_xor_sync(0xffffffffu, p, o);
        if (lane == n) mydot = p;
    }
    if (lane < NQh) {
        float a = tanhf(mydot + qmapb[lane]);
        float s, c;
        if (side == 0) {
            float mix = 1.f / (1.f + __expf(-*es_ptr));
            float w = (1.f / (1.f + __expf(-qw[h * NQh + lane]))) * (1.0f / NQh) * mix;
            sincosf(a + ph[h * NQh + lane], &s, &c);
            g_fQ[(size_t)r * NF + lane]       = w * c;
            g_fQ[(size_t)r * NF + NQh + lane] = w * s;
        } else {
            sincosf(a, &s, &c);
            g_fK[(size_t)r * NF + lane]       = c;
            g_fK[(size_t)r * NF + NQh + lane] = s;
        }
    }
}

// ---------------- zero out2 --------------------------------------------------
__global__ void zero_out2_kernel(float* __restrict__ out2) {
    int idx = blockIdx.x * blockDim.x + threadIdx.x;
    if (idx < BB * SS * SS / 4)
        ((float4*)out2)[idx] = make_float4(0.f, 0.f, 0.f, 0.f);
}

// ---------------- fused attention (512 thr, depth-2 gmem pipeline) ----------
__global__ __launch_bounds__(ATHREADS) void attn_kernel(const float* __restrict__ es_ptr,
                                                        float* __restrict__ out2) {
    extern __shared__ float P[];                       // [64][PROW]
    unsigned* Ks   = (unsigned*)(P + 64 * PROW);       // phase 1
    float*    entT = (float*)(Ks + 64 * KPITCH);       // phase 1 LUT
    unsigned* Vs0  = (unsigned*)(P + 64 * PROW);       // phase 3
    unsigned* Vs1  = Vs0 + 64 * VPITCH;

    int bh = blockIdx.y;
    int b = bh >> 4, h = bh & 15;
    int i0 = blockIdx.x * 64;
    const float* Qp  = g_Q  + (size_t)bh * SS * HDIM;
    const float* Kp  = g_K  + (size_t)bh * SS * HDIM;
    const float* Vtp = g_V  + (size_t)bh * HDIM * SS;  // [d][s]
    const float* Fqp = g_fQ + (size_t)bh * SS * NF;
    const float* Fkp = g_fK + (size_t)bh * SS * NF;
    float* o2p = out2 + (size_t)b * SS * SS;

    int tid = threadIdx.x;
    int wid = tid >> 5, lane = tid & 31;
    int wm = wid & 3, wn = wid >> 2;                   // 4m x 4n
    int g = lane >> 2, tg = lane & 3;
    int a_row = lane & 15, a_koff = (lane >> 4) * 4;
    int b_nr  = (lane & 7) + ((lane >> 4) << 3);
    int b_koff = ((lane >> 3) & 1) * 4;
    unsigned PBase   = (unsigned)__cvta_generic_to_shared(P);
    unsigned KsBase  = (unsigned)__cvta_generic_to_shared(Ks);
    unsigned VsBase0 = (unsigned)__cvta_generic_to_shared(Vs0);
    unsigned VsBase1 = (unsigned)__cvta_generic_to_shared(Vs1);

    float es  = *es_ptr;
    float mix = 1.f / (1.f + __expf(-es));
    float ca  = (1.f - mix) * 0.125f;

    for (int t = tid; t < ENTN; t += ATHREADS)
        entT[t] = __expf(-0.1f * fabsf((float)(i0 - 767 + t)));

    // staging index helpers
    int sK_r = 0, sK_c4 = 0, sF_r = 0, sF_c4 = 0;
    {
        sK_r = tid >> 4;            sK_c4 = (tid & 15) * 4;         // rows 0..31 (it=0)
        sF_r = tid >> 2;            sF_c4 = (tid & 3) * 4;          // Fk rows (tid<256)
    }

    // ---- stage Q(*ca)+Fq into Ks, preload persistent a-fragments -----------
    {
        #pragma unroll
        for (int it = 0; it < 2; it++) {
            int fid = tid + ATHREADS * it;
            int r = fid >> 4, c4 = (fid & 15) * 4;
            float4 f = *(const float4*)&Qp[(size_t)(i0 + r) * HDIM + c4];
            *(uint4*)&Ks[r * KPITCH + c4] =
                make_uint4(f2tf32(ca * f.x), f2tf32(ca * f.y),
                           f2tf32(ca * f.z), f2tf32(ca * f.w));
        }
        if (tid < 256) {
            float4 f = *(const float4*)&Fqp[(size_t)(i0 + sF_r) * NF + sF_c4];
            *(uint4*)&Ks[sF_r * KPITCH + 64 + sF_c4] =
                make_uint4(f2tf32(f.x), f2tf32(f.y), f2tf32(f.z), f2tf32(f.w));
        }
    }
    __syncthreads();
    unsigned afr[10][4];
    #pragma unroll
    for (int s = 0; s < 10; s++) {
        int r = wm * 16 + g, c = s * 8 + tg;
        afr[s][0] = Ks[r * KPITCH + c];
        afr[s][1] = Ks[(r + 8) * KPITCH + c];
        afr[s][2] = Ks[r * KPITCH + c + 4];
        afr[s][3] = Ks[(r + 8) * KPITCH + c + 4];
    }
    __syncthreads();

    // ---- phase 1: scores over 12 K-chunks (depth-2 prefetch) ---------------
    float4 rcA[2], rqA, rcB[2], rqB;
    {
        // chunk 0: load + STS
        #pragma unroll
        for (int it = 0; it < 2; it++) {
            int fid = tid + ATHREADS * it;
            int r = fid >> 4, c4 = (fid & 15) * 4;
            rcA[it] = *(const float4*)&Kp[(size_t)r * HDIM + c4];
        }
        if (tid < 256)
            rqA = *(const float4*)&Fkp[(size_t)sF_r * NF + sF_c4];
        #pragma unroll
        for (int it = 0; it < 2; it++) {
            int fid = tid + ATHREADS * it;
            int r = fid >> 4, c4 = (fid & 15) * 4;
            *(uint4*)&Ks[r * KPITCH + c4] =
                make_uint4(f2tf32(rcA[it].x), f2tf32(rcA[it].y),
                           f2tf32(rcA[it].z), f2tf32(rcA[it].w));
        }
        if (tid < 256)
            *(uint4*)&Ks[sF_r * KPITCH + 64 + sF_c4] =
                make_uint4(f2tf32(rqA.x), f2tf32(rqA.y), f2tf32(rqA.z), f2tf32(rqA.w));
        // chunk 1 -> rcA (long latency; covered by barrier + chunk-0 compute)
        #pragma unroll
        for (int it = 0; it < 2; it++) {
            int fid = tid + ATHREADS * it;
            int r = fid >> 4, c4 = (fid & 15) * 4;
            rcA[it] = *(const float4*)&Kp[(size_t)(64 + r) * HDIM + c4];
        }
        if (tid < 256)
            rqA = *(const float4*)&Fkp[(size_t)(64 + sF_r) * NF + sF_c4];
        __syncthreads();
    }
    for (int jc = 0; jc < 12; jc++) {
        int j0 = jc * 64;
        if (jc + 2 < 12) {              // prefetch chunk jc+2 (deep)
            int jn = j0 + 128;
            #pragma unroll
            for (int it = 0; it < 2; it++) {
                int fid = tid + ATHREADS * it;
                int r = fid >> 4, c4 = (fid & 15) * 4;
                rcB[it] = *(const float4*)&Kp[(size_t)(jn + r) * HDIM + c4];
            }
            if (tid < 256)
                rqB = *(const float4*)&Fkp[(size_t)(jn + sF_r) * NF + sF_c4];
        }
        float accC[2][4] = {}, accQ[2][4] = {};
        #pragma unroll
        for (int s = 0; s < 10; s++) {
            int kc = s * 8;
            unsigned bf[2][2];
            ldsm_x4(bf[0][0], bf[0][1], bf[1][0], bf[1][1],
                    KsBase + ((wn * 16 + b_nr) * KPITCH + kc + b_koff) * 4);
            #pragma unroll
            for (int nt = 0; nt < 2; nt++) {
                if (s < 8)
                    mma_tf32(accC[nt][0], accC[nt][1], accC[nt][2], accC[nt][3],
                             afr[s][0], afr[s][1], afr[s][2], afr[s][3],
                             bf[nt][0], bf[nt][1]);
                else
                    mma_tf32(accQ[nt][0], accQ[nt][1], accQ[nt][2], accQ[nt][3],
                             afr[s][0], afr[s][1], afr[s][2], afr[s][3],
                             bf[nt][0], bf[nt][1]);
            }
        }
        #pragma unroll
        for (int nt = 0; nt < 2; nt++) {
            int r  = wm * 16 + g;
            int cl = wn * 16 + nt * 8 + tg * 2;
            #pragma unroll
            for (int hrow = 0; hrow < 2; hrow++) {
                int rr = r + hrow * 8;
                int base = rr + 767 - j0 - cl;
                float e0 = entT[base];
                float e1 = entT[base - 1];
                float2 st;
                st.x = accC[nt][hrow * 2]     + e0 * accQ[nt][hrow * 2];
                st.y = accC[nt][hrow * 2 + 1] + e1 * accQ[nt][hrow * 2 + 1];
                *(float2*)&P[rr * PROW + j0 + cl] = st;
            }
        }
        __syncthreads();                // Ks readers done
        if (jc + 1 < 12) {              // stage chunk jc+1 (loaded 1 iter ago)
            #pragma unroll
            for (int it = 0; it < 2; it++) {
                int fid = tid + ATHREADS * it;
                int r = fid >> 4, c4 = (fid & 15) * 4;
                *(uint4*)&Ks[r * KPITCH + c4] =
                    make_uint4(f2tf32(rcA[it].x), f2tf32(rcA[it].y),
                               f2tf32(rcA[it].z), f2tf32(rcA[it].w));
            }
            if (tid < 256)
                *(uint4*)&Ks[sF_r * KPITCH + 64 + sF_c4] =
                    make_uint4(f2tf32(rqA.x), f2tf32(rqA.y),
                               f2tf32(rqA.z), f2tf32(rqA.w));
        }
        __syncthreads();
        rcA[0] = rcB[0]; rcA[1] = rcB[1]; rqA = rqB;   // rotate queue
    }

    // ---- prefetch V chunk 0 (hidden under phase 2) --------------------------
    float4 vA[2], vB[2];
    #pragma unroll
    for (int it = 0; it < 2; it++) {
        int fid = tid + ATHREADS * it;
        int d = fid >> 4, c4 = (fid & 15) * 4;
        vA[it] = *(const float4*)&Vtp[(size_t)d * SS + c4];
    }

    // ---- phase 2: softmax + head-mean reduction into out2 (4 rows/warp) ----
    for (int rr = wid; rr < 64; rr += 16) {
        float4* row4 = (float4*)(P + rr * PROW);
        float4 v[6];
        float m = -1e30f;
        #pragma unroll
        for (int u = 0; u < 6; u++) {
            v[u] = row4[lane + u * 32];
            m = fmaxf(m, fmaxf(fmaxf(v[u].x, v[u].y), fmaxf(v[u].z, v[u].w)));
        }
        #pragma unroll
        for (int o = 16; o; o >>= 1) m = fmaxf(m, __shfl_xor_sync(0xffffffffu, m, o));
        float ssum = 0.f;
        #pragma unroll
        for (int u = 0; u < 6; u++) {
            v[u].x = __expf(v[u].x - m); v[u].y = __expf(v[u].y - m);
            v[u].z = __expf(v[u].z - m); v[u].w = __expf(v[u].w - m);
            ssum += (v[u].x + v[u].y) + (v[u].z + v[u].w);
        }
        #pragma unroll
        for (int o = 16; o; o >>= 1) ssum += __shfl_xor_sync(0xffffffffu, ssum, o);
        float inv = __frcp_rn(ssum);
        float* o2row = o2p + (size_t)(i0 + rr) * SS;
        #pragma unroll
        for (int u = 0; u < 6; u++) {
            float4 t;
            t.x = __uint_as_float(f2tf32(v[u].x * inv));
            t.y = __uint_as_float(f2tf32(v[u].y * inv));
            t.z = __uint_as_float(f2tf32(v[u].z * inv));
            t.w = __uint_as_float(f2tf32(v[u].w * inv));
            row4[lane + u * 32] = t;
            red_add_v4(o2row + (lane + u * 32) * 4,
                       t.x * (1.0f / HH), t.y * (1.0f / HH),
                       t.z * (1.0f / HH), t.w * (1.0f / HH));
        }
    }
    __syncthreads();                    // P final; Ks region dead -> Vs usable

    // ---- phase 3: AV, depth-2 V prefetch ------------------------------------
    float acc[2][4] = {};
    {
        // STS chunk 0 (loaded before phase 2), then load chunk 1 -> vA
        #pragma unroll
        for (int it = 0; it < 2; it++) {
            int fid = tid + ATHREADS * it;
            int d = fid >> 4, c4 = (fid & 15) * 4;
            *(uint4*)&Vs0[d * VPITCH + c4] =
                make_uint4(f2tf32(vA[it].x), f2tf32(vA[it].y),
                           f2tf32(vA[it].z), f2tf32(vA[it].w));
        }
        #pragma unroll
        for (int it = 0; it < 2; it++) {
            int fid = tid + ATHREADS * it;
            int d = fid >> 4, c4 = (fid & 15) * 4;
            vA[it] = *(const float4*)&Vtp[(size_t)d * SS + 64 + c4];
        }
        __syncthreads();
    }
    for (int c = 0; c < 12; c++) {
        int k0 = c * 64;
        unsigned curB = (c & 1) ? VsBase1 : VsBase0;
        unsigned* nxt = (c & 1) ? Vs0 : Vs1;
        if (c + 2 < 12) {               // deep prefetch chunk c+2
            int kn = k0 + 128;
            #pragma unroll
            for (int it = 0; it < 2; it++) {
                int fid = tid + ATHREADS * it;
                int d = fid >> 4, c4 = (fid & 15) * 4;
                vB[it] = *(const float4*)&Vtp[(size_t)d * SS + kn + c4];
            }
        }
        #pragma unroll
        for (int s = 0; s < 8; s++) {
            int kc = s * 8;
            unsigned af[4];
            ldsm_x4(af[0], af[1], af[2], af[3],
                    PBase + ((wm * 16 + a_row) * PROW + k0 + kc + a_koff) * 4);
            unsigned bf[2][2];
            ldsm_x4(bf[0][0], bf[0][1], bf[1][0], bf[1][1],
                    curB + ((wn * 16 + b_nr) * VPITCH + kc + b_koff) * 4);
            #pragma unroll
            for (int nt = 0; nt < 2; nt++)
                mma_tf32(acc[nt][0], acc[nt][1], acc[nt][2], acc[nt][3],
                         af[0], af[1], af[2], af[3], bf[nt][0], bf[nt][1]);
        }
        if (c + 1 < 12) {               // stage chunk c+1 (loaded 1 iter ago)
            #pragma unroll
            for (int it = 0; it < 2; it++) {
                int fid = tid + ATHREADS * it;
                int d = fid >> 4, c4 = (fid & 15) * 4;
                *(uint4*)&nxt[d * VPITCH + c4] =
                    make_uint4(f2tf32(vA[it].x), f2tf32(vA[it].y),
                               f2tf32(vA[it].z), f2tf32(vA[it].w));
            }
        }
        __syncthreads();
        vA[0] = vB[0]; vA[1] = vB[1];
    }
    #pragma unroll
    for (int nt = 0; nt < 2; nt++) {
        int r = wm * 16 + g;
        int d0 = wn * 16 + nt * 8 + tg * 2;
        #pragma unroll
        for (int hrow = 0; hrow < 2; hrow++) {
            int s_ = i0 + r + hrow * 8;
            *(float2*)&g_att[(size_t)(b * SS + s_) * DDIM + h * HDIM + d0] =
                make_float2(acc[nt][hrow * 2], acc[nt][hrow * 2 + 1]);
        }
    }
}

// ---------------- launch -----------------------------------------------------
extern "C" void kernel_launch(void* const* d_in, const int* in_sizes, int n_in,
                              void* d_out, int out_size) {
    const float* query = (const float*)d_in[0];
    const float* key   = (const float*)d_in[1];
    const float* value = (const float*)d_in[2];
    const float* Wq = (const float*)d_in[3];
    const float* bq = (const float*)d_in[4];
    const float* Wk = (const float*)d_in[5];
    const float* bk = (const float*)d_in[6];
    const float* Wv = (const float*)d_in[7];
    const float* bv = (const float*)d_in[8];
    const float* Wo = (const float*)d_in[9];
    const float* bo = (const float*)d_in[10];
    const float* qmapW = (const float*)d_in[11];
    const float* qmapb = (const float*)d_in[12];
    const float* qw    = (const float*)d_in[13];
    const float* ph    = (const float*)d_in[14];
    const float* es    = (const float*)d_in[15];

    float* out  = (float*)d_out;
    float* out2 = out + (size_t)MM * DDIM;

    {
        int n = BB * SS * SS / 4;
        zero_out2_kernel<<<(n + 255) / 256, 256>>>(out2);
    }
    proj_kernel<<<dim3(DDIM / 128, MM / 128, 3), 256>>>(query, key, value,
                                                        Wq, bq, Wk, bk, Wv, bv);
    {
        int nrows = 2 * BHn * SS;
        qfeat_kernel<<<nrows / 8, 256>>>(qmapW, qmapb, qw, ph, es);
    }
    {
        size_t smem = (size_t)64 * PROW * 4 + (size_t)2 * 64 * VPITCH * 4; // 232448
        cudaFuncSetAttribute(attn_kernel,
                             cudaFuncAttributeMaxDynamicSharedMemorySize, (int)smem);
        attn_kernel<<<dim3(SS / 64, BHn), ATHREADS, smem>>>(es, out2);
    }
    outproj_kernel<<<dim3(DDIM / 128, MM / 128), 256>>>(Wo, bo, out);
}

// round 15
// speedup vs baseline: 1.1709x; 1.0434x over previous
#include <cuda_runtime.h>
#include <math.h>

#define BB   2
#define SS   768
#define DDIM 1024
#define HH   16
#define HDIM 64
#define NQh  8
#define NF   16
#define BHn  (BB*HH)     // 32
#define MM   (BB*SS)     // 1536
#define PROW 772         // 772 % 32 == 4 -> conflict-free ldmatrix rows
#define SPITCH 20
#define KPITCH 84        // 84 % 32 == 20 -> conflict-free
#define VPITCH 68        // 68 % 32 == 4  -> conflict-free
#define ENTN 831
#define ATHREADS 512

// ---------------- scratch ----------------------------------------------------
__device__ float g_Q[BHn*SS*HDIM];      // [bh][s][d]
__device__ float g_K[BHn*SS*HDIM];      // [bh][s][d]
__device__ float g_V[BHn*SS*HDIM];      // [bh][d][s]  (TRANSPOSED)
__device__ float g_fQ[BHn*SS*NF];
__device__ float g_fK[BHn*SS*NF];
__device__ float g_att[MM*DDIM];

// ---------------- helpers ----------------------------------------------------
__device__ __forceinline__ unsigned f2tf32(float f) {
    unsigned u;
    asm("cvt.rna.tf32.f32 %0, %1;" : "=r"(u) : "f"(f));
    return u;
}

__device__ __forceinline__ void mma_tf32(float& c0, float& c1, float& c2, float& c3,
                                         unsigned a0, unsigned a1, unsigned a2, unsigned a3,
                                         unsigned b0, unsigned b1) {
    asm volatile("mma.sync.aligned.m16n8k8.row.col.f32.tf32.tf32.f32 "
                 "{%0,%1,%2,%3}, {%4,%5,%6,%7}, {%8,%9}, {%0,%1,%2,%3};\n"
                 : "+f"(c0), "+f"(c1), "+f"(c2), "+f"(c3)
                 : "r"(a0), "r"(a1), "r"(a2), "r"(a3), "r"(b0), "r"(b1));
}

__device__ __forceinline__ void ldsm_x4(unsigned& r0, unsigned& r1,
                                        unsigned& r2, unsigned& r3, unsigned addr) {
    asm volatile("ldmatrix.sync.aligned.m8n8.x4.shared.b16 {%0,%1,%2,%3}, [%4];"
                 : "=r"(r0), "=r"(r1), "=r"(r2), "=r"(r3) : "r"(addr));
}

__device__ __forceinline__ void red_add_v4(float* p, float x, float y, float z, float w) {
    asm volatile("red.global.add.v4.f32 [%0], {%1,%2,%3,%4};"
                 :: "l"(p), "f"(x), "f"(y), "f"(z), "f"(w) : "memory");
}

__device__ __forceinline__ void red_add_v2(float* p, float x, float y) {
    asm volatile("red.global.add.v2.f32 [%0], {%1,%2};"
                 :: "l"(p), "f"(x), "f"(y) : "memory");
}

// ============================================================================
// tf32 GEMM core: 128x128 tile, 8 warps, ldmatrix fragments, ping-pong smem.
// K range [KBASE, KBASE + NCHUNK*16).
// ============================================================================
#define GEMM_BODY(LOAD_A0, LOAD_A1, LOAD_B, NCHUNK, KBASE)                       \
    float acc[4][4][4] = {};                                                     \
    int tid = threadIdx.x;                                                       \
    int wid = tid >> 5, lane = tid & 31;                                         \
    int wm = wid & 1, wnw = wid >> 1;                                            \
    int ar = tid >> 2, ac = (tid & 3) * 4;                                       \
    int bn = tid & 127, bk0 = (tid >> 7) * 8;                                    \
    int a_row = lane & 15, a_koff = (lane >> 4) * 4;                             \
    int b_nr  = (lane & 7) + ((lane >> 4) << 3);                                 \
    int b_koff = ((lane >> 3) & 1) * 4;                                          \
    unsigned aBase0 = (unsigned)__cvta_generic_to_shared(As0);                   \
    unsigned aBase1 = (unsigned)__cvta_generic_to_shared(As1);                   \
    unsigned bBase0 = (unsigned)__cvta_generic_to_shared(Bs0);                   \
    unsigned bBase1 = (unsigned)__cvta_generic_to_shared(Bs1);                   \
    float4 pa0, pa1; float pb[8];                                                \
    { int kg = (KBASE);                                                          \
      pa0 = LOAD_A0(kg); pa1 = LOAD_A1(kg);                                      \
      _Pragma("unroll") for (int j = 0; j < 8; j++) pb[j] = LOAD_B(kg, j); }     \
    { unsigned* As = As0; unsigned* Bs = Bs0;                                    \
      *(uint4*)&As[ar * SPITCH + ac] =                                           \
          make_uint4(f2tf32(pa0.x), f2tf32(pa0.y), f2tf32(pa0.z), f2tf32(pa0.w));\
      *(uint4*)&As[(ar + 64) * SPITCH + ac] =                                    \
          make_uint4(f2tf32(pa1.x), f2tf32(pa1.y), f2tf32(pa1.z), f2tf32(pa1.w));\
      *(uint4*)&Bs[bn * SPITCH + bk0] =                                          \
          make_uint4(f2tf32(pb[0]), f2tf32(pb[1]), f2tf32(pb[2]), f2tf32(pb[3]));\
      *(uint4*)&Bs[bn * SPITCH + bk0 + 4] =                                      \
          make_uint4(f2tf32(pb[4]), f2tf32(pb[5]), f2tf32(pb[6]), f2tf32(pb[7]));}\
    __syncthreads();                                                             \
    for (int ch = 0; ch < (NCHUNK); ch++) {                                      \
        int buf = ch & 1;                                                        \
        if (ch + 1 < (NCHUNK)) {                                                 \
            int kg = (KBASE) + (ch + 1) * 16;                                    \
            pa0 = LOAD_A0(kg); pa1 = LOAD_A1(kg);                                \
            _Pragma("unroll") for (int j = 0; j < 8; j++) pb[j] = LOAD_B(kg, j); \
        }                                                                        \
        unsigned aB = buf ? aBase1 : aBase0;                                     \
        unsigned bB = buf ? bBase1 : bBase0;                                     \
        _Pragma("unroll")                                                        \
        for (int ks = 0; ks < 2; ks++) {                                         \
            int kc = ks * 8;                                                     \
            unsigned af[4][4];                                                   \
            _Pragma("unroll")                                                    \
            for (int mt = 0; mt < 4; mt++)                                       \
                ldsm_x4(af[mt][0], af[mt][1], af[mt][2], af[mt][3],              \
                    aB + ((wm * 64 + mt * 16 + a_row) * SPITCH + kc + a_koff) * 4);\
            unsigned bf[4][2];                                                   \
            _Pragma("unroll")                                                    \
            for (int p = 0; p < 2; p++)                                          \
                ldsm_x4(bf[2 * p][0], bf[2 * p][1], bf[2 * p + 1][0],            \
                        bf[2 * p + 1][1],                                        \
                    bB + ((wnw * 32 + p * 16 + b_nr) * SPITCH + kc + b_koff) * 4);\
            _Pragma("unroll")                                                    \
            for (int mt = 0; mt < 4; mt++)                                       \
                _Pragma("unroll")                                                \
                for (int nt = 0; nt < 4; nt++)                                   \
                    mma_tf32(acc[mt][nt][0], acc[mt][nt][1],                     \
                             acc[mt][nt][2], acc[mt][nt][3],                     \
                             af[mt][0], af[mt][1], af[mt][2], af[mt][3],         \
                             bf[nt][0], bf[nt][1]);                              \
        }                                                                        \
        if (ch + 1 < (NCHUNK)) {                                                 \
            unsigned* As = buf ? As0 : As1;                                      \
            unsigned* Bs = buf ? Bs0 : Bs1;                                      \
            *(uint4*)&As[ar * SPITCH + ac] =                                     \
                make_uint4(f2tf32(pa0.x), f2tf32(pa0.y), f2tf32(pa0.z), f2tf32(pa0.w));\
            *(uint4*)&As[(ar + 64) * SPITCH + ac] =                              \
                make_uint4(f2tf32(pa1.x), f2tf32(pa1.y), f2tf32(pa1.z), f2tf32(pa1.w));\
            *(uint4*)&Bs[bn * SPITCH + bk0] =                                    \
                make_uint4(f2tf32(pb[0]), f2tf32(pb[1]), f2tf32(pb[2]), f2tf32(pb[3]));\
            *(uint4*)&Bs[bn * SPITCH + bk0 + 4] =                                \
                make_uint4(f2tf32(pb[4]), f2tf32(pb[5]), f2tf32(pb[6]), f2tf32(pb[7]));\
        }                                                                        \
        __syncthreads();                                                         \
    }

// ---------------- fused QKV projection (full K) ------------------------------
__global__ __launch_bounds__(256, 2) void proj_kernel(
        const float* __restrict__ q, const float* __restrict__ k,
        const float* __restrict__ v,
        const float* __restrict__ Wq, const float* __restrict__ bq,
        const float* __restrict__ Wk, const float* __restrict__ bk,
        const float* __restrict__ Wv, const float* __restrict__ bv) {
    int which = blockIdx.z;
    const float* A    = (which == 0) ? q  : (which == 1) ? k  : v;
    const float* W    = (which == 0) ? Wq : (which == 1) ? Wk : Wv;
    const float* bias = (which == 0) ? bq : (which == 1) ? bk : bv;
    float*       out  = (which == 0) ? g_Q : (which == 1) ? g_K : g_V;

    __shared__ unsigned As0[128 * SPITCH], As1[128 * SPITCH];
    __shared__ unsigned Bs0[128 * SPITCH], Bs1[128 * SPITCH];
    int row0 = blockIdx.y * 128, col0 = blockIdx.x * 128;

#define LA0(kg) (*(const float4*)&A[(size_t)(row0 + ar) * DDIM + (kg) + ac])
#define LA1(kg) (*(const float4*)&A[(size_t)(row0 + 64 + ar) * DDIM + (kg) + ac])
#define LB(kg, j) (W[(size_t)((kg) + bk0 + (j)) * DDIM + col0 + bn])
    GEMM_BODY(LA0, LA1, LB, DDIM / 16, 0)
#undef LA0
#undef LA1
#undef LB

    int g = lane >> 2, tg = lane & 3;
    #pragma unroll
    for (int mt = 0; mt < 4; mt++)
        #pragma unroll
        for (int nt = 0; nt < 4; nt++) {
            int gm = row0 + wm * 64 + mt * 16 + g;
            int gn = col0 + wnw * 32 + nt * 8 + tg * 2;
            #pragma unroll
            for (int hrow = 0; hrow < 2; hrow++) {
                int m = gm + hrow * 8;
                int b = m / SS, s = m % SS;
                int h = gn >> 6, d = gn & 63;
                if (which == 2) {   // V transposed: [bh][d][s]
                    #pragma unroll
                    for (int j = 0; j < 2; j++)
                        out[((size_t)(b * HH + h) * HDIM + d + j) * SS + s] =
                            acc[mt][nt][hrow * 2 + j] + bias[gn + j];
                } else {            // Q/K: [bh][s][d]
                    float2 st;
                    st.x = acc[mt][nt][hrow * 2]     + bias[gn];
                    st.y = acc[mt][nt][hrow * 2 + 1] + bias[gn + 1];
                    *(float2*)&out[((size_t)(b * HH + h) * SS + s) * HDIM + d] = st;
                }
            }
        }
}

// ---------------- outproj, split-K=2 (red.add into zeroed out) ---------------
__global__ __launch_bounds__(256, 2) void outproj_kernel(const float* __restrict__ Wo,
                                                         const float* __restrict__ bo,
                                                         float* __restrict__ out) {
    __shared__ unsigned As0[128 * SPITCH], As1[128 * SPITCH];
    __shared__ unsigned Bs0[128 * SPITCH], Bs1[128 * SPITCH];
    int row0 = blockIdx.y * 128, col0 = blockIdx.x * 128;
    int kbase = blockIdx.z * (DDIM / 2);

#define LA0(kg) (*(const float4*)&g_att[(size_t)(row0 + ar) * DDIM + (kg) + ac])
#define LA1(kg) (*(const float4*)&g_att[(size_t)(row0 + 64 + ar) * DDIM + (kg) + ac])
#define LB(kg, j) (Wo[(size_t)((kg) + bk0 + (j)) * DDIM + col0 + bn])
    GEMM_BODY(LA0, LA1, LB, DDIM / 32, kbase)
#undef LA0
#undef LA1
#undef LB

    int g = lane >> 2, tg = lane & 3;
    bool addb = (blockIdx.z == 0);
    #pragma unroll
    for (int mt = 0; mt < 4; mt++)
        #pragma unroll
        for (int nt = 0; nt < 4; nt++) {
            int gm = row0 + wm * 64 + mt * 16 + g;
            int gn = col0 + wnw * 32 + nt * 8 + tg * 2;
            #pragma unroll
            for (int hrow = 0; hrow < 2; hrow++) {
                int m = gm + hrow * 8;
                float x = acc[mt][nt][hrow * 2]     + (addb ? bo[gn]     : 0.f);
                float y = acc[mt][nt][hrow * 2 + 1] + (addb ? bo[gn + 1] : 0.f);
                red_add_v2(&out[(size_t)m * DDIM + gn], x, y);
            }
        }
}

// ---------------- quantum features (warp-per-row) + output zero-fill ---------
__global__ __launch_bounds__(256) void qfeat_kernel(
        const float* __restrict__ qmapW, const float* __restrict__ qmapb,
        const float* __restrict__ qw, const float* __restrict__ ph,
        const float* __restrict__ es_ptr, float* __restrict__ outbuf) {
    // zero d_out: out [MM*DDIM] + out2 [BB*SS*SS] floats (poisoned by harness)
    {
        int gtid = blockIdx.x * blockDim.x + threadIdx.x;
        int n1 = MM * DDIM / 4;              // 393216 float4
        int n2 = BB * SS * SS / 4;           // 294912 float4
        if (gtid < n1)
            ((float4*)outbuf)[gtid] = make_float4(0.f, 0.f, 0.f, 0.f);
        int g2 = gtid - n1;
        if (g2 >= 0 && g2 < n2)
            ((float4*)(outbuf + (size_t)MM * DDIM))[g2] = make_float4(0.f, 0.f, 0.f, 0.f);
    }
    int gw   = (blockIdx.x * blockDim.x + threadIdx.x) >> 5;
    int lane = threadIdx.x & 31;
    if (gw >= 2 * BHn * SS) return;
    int side = gw / (BHn * SS);
    int r    = gw % (BHn * SS);
    int h    = (r / SS) % HH;
    const float* row = ((side == 0) ? g_Q : g_K) + (size_t)r * HDIM;
    float rv0 = row[lane], rv1 = row[lane + 32];

    float mydot = 0.f;
    #pragma unroll
    for (int n = 0; n < NQh; n++) {
        float p = rv0 * qmapW[lane * NQh + n] + rv1 * qmapW[(lane + 32) * NQh + n];
        #pragma unroll
        for (int o = 16; o; o >>= 1) p += __shfl_xor_sync(0xffffffffu, p, o);
        if (lane == n) mydot = p;
    }
    if (lane < NQh) {
        float a = tanhf(mydot + qmapb[lane]);
        float s, c;
        if (side == 0) {
            float mix = 1.f / (1.f + __expf(-*es_ptr));
            float w = (1.f / (1.f + __expf(-qw[h * NQh + lane]))) * (1.0f / NQh) * mix;
            sincosf(a + ph[h * NQh + lane], &s, &c);
            g_fQ[(size_t)r * NF + lane]       = w * c;
            g_fQ[(size_t)r * NF + NQh + lane] = w * s;
        } else {
            sincosf(a, &s, &c);
            g_fK[(size_t)r * NF + lane]       = c;
            g_fK[(size_t)r * NF + NQh + lane] = s;
        }
    }
}

// ---------------- fused attention (512 thr, depth-2 gmem pipeline) ----------
__global__ __launch_bounds__(ATHREADS) void attn_kernel(const float* __restrict__ es_ptr,
                                                        float* __restrict__ out2) {
    extern __shared__ float P[];                       // [64][PROW]
    unsigned* Ks   = (unsigned*)(P + 64 * PROW);       // phase 1
    float*    entT = (float*)(Ks + 64 * KPITCH);       // phase 1 LUT
    unsigned* Vs0  = (unsigned*)(P + 64 * PROW);       // phase 3
    unsigned* Vs1  = Vs0 + 64 * VPITCH;

    int bh = blockIdx.y;
    int b = bh >> 4, h = bh & 15;
    int i0 = blockIdx.x * 64;
    const float* Qp  = g_Q  + (size_t)bh * SS * HDIM;
    const float* Kp  = g_K  + (size_t)bh * SS * HDIM;
    const float* Vtp = g_V  + (size_t)bh * HDIM * SS;  // [d][s]
    const float* Fqp = g_fQ + (size_t)bh * SS * NF;
    const float* Fkp = g_fK + (size_t)bh * SS * NF;
    float* o2p = out2 + (size_t)b * SS * SS;

    int tid = threadIdx.x;
    int wid = tid >> 5, lane = tid & 31;
    int wm = wid & 3, wn = wid >> 2;                   // 4m x 4n
    int g = lane >> 2, tg = lane & 3;
    int a_row = lane & 15, a_koff = (lane >> 4) * 4;
    int b_nr  = (lane & 7) + ((lane >> 4) << 3);
    int b_koff = ((lane >> 3) & 1) * 4;
    unsigned PBase   = (unsigned)__cvta_generic_to_shared(P);
    unsigned KsBase  = (unsigned)__cvta_generic_to_shared(Ks);
    unsigned VsBase0 = (unsigned)__cvta_generic_to_shared(Vs0);
    unsigned VsBase1 = (unsigned)__cvta_generic_to_shared(Vs1);

    float es  = *es_ptr;
    float mix = 1.f / (1.f + __expf(-es));
    float ca  = (1.f - mix) * 0.125f;

    for (int t = tid; t < ENTN; t += ATHREADS)
        entT[t] = __expf(-0.1f * fabsf((float)(i0 - 767 + t)));

    int sF_r = tid >> 2, sF_c4 = (tid & 3) * 4;

    {
        #pragma unroll
        for (int it = 0; it < 2; it++) {
            int fid = tid + ATHREADS * it;
            int r = fid >> 4, c4 = (fid & 15) * 4;
            float4 f = *(const float4*)&Qp[(size_t)(i0 + r) * HDIM + c4];
            *(uint4*)&Ks[r * KPITCH + c4] =
                make_uint4(f2tf32(ca * f.x), f2tf32(ca * f.y),
                           f2tf32(ca * f.z), f2tf32(ca * f.w));
        }
        if (tid < 256) {
            float4 f = *(const float4*)&Fqp[(size_t)(i0 + sF_r) * NF + sF_c4];
            *(uint4*)&Ks[sF_r * KPITCH + 64 + sF_c4] =
                make_uint4(f2tf32(f.x), f2tf32(f.y), f2tf32(f.z), f2tf32(f.w));
        }
    }
    __syncthreads();
    unsigned afr[10][4];
    #pragma unroll
    for (int s = 0; s < 10; s++) {
        int r = wm * 16 + g, c = s * 8 + tg;
        afr[s][0] = Ks[r * KPITCH + c];
        afr[s][1] = Ks[(r + 8) * KPITCH + c];
        afr[s][2] = Ks[r * KPITCH + c + 4];
        afr[s][3] = Ks[(r + 8) * KPITCH + c + 4];
    }
    __syncthreads();

    float4 rcA[2], rqA, rcB[2], rqB;
    {
        #pragma unroll
        for (int it = 0; it < 2; it++) {
            int fid = tid + ATHREADS * it;
            int r = fid >> 4, c4 = (fid & 15) * 4;
            rcA[it] = *(const float4*)&Kp[(size_t)r * HDIM + c4];
        }
        if (tid < 256)
            rqA = *(const float4*)&Fkp[(size_t)sF_r * NF + sF_c4];
        #pragma unroll
        for (int it = 0; it < 2; it++) {
            int fid = tid + ATHREADS * it;
            int r = fid >> 4, c4 = (fid & 15) * 4;
            *(uint4*)&Ks[r * KPITCH + c4] =
                make_uint4(f2tf32(rcA[it].x), f2tf32(rcA[it].y),
                           f2tf32(rcA[it].z), f2tf32(rcA[it].w));
        }
        if (tid < 256)
            *(uint4*)&Ks[sF_r * KPITCH + 64 + sF_c4] =
                make_uint4(f2tf32(rqA.x), f2tf32(rqA.y), f2tf32(rqA.z), f2tf32(rqA.w));
        #pragma unroll
        for (int it = 0; it < 2; it++) {
            int fid = tid + ATHREADS * it;
            int r = fid >> 4, c4 = (fid & 15) * 4;
            rcA[it] = *(const float4*)&Kp[(size_t)(64 + r) * HDIM + c4];
        }
        if (tid < 256)
            rqA = *(const float4*)&Fkp[(size_t)(64 + sF_r) * NF + sF_c4];
        __syncthreads();
    }
    for (int jc = 0; jc < 12; jc++) {
        int j0 = jc * 64;
        if (jc + 2 < 12) {
            int jn = j0 + 128;
            #pragma unroll
            for (int it = 0; it < 2; it++) {
                int fid = tid + ATHREADS * it;
                int r = fid >> 4, c4 = (fid & 15) * 4;
                rcB[it] = *(const float4*)&Kp[(size_t)(jn + r) * HDIM + c4];
            }
            if (tid < 256)
                rqB = *(const float4*)&Fkp[(size_t)(jn + sF_r) * NF + sF_c4];
        }
        float accC[2][4] = {}, accQ[2][4] = {};
        #pragma unroll
        for (int s = 0; s < 10; s++) {
            int kc = s * 8;
            unsigned bf[2][2];
            ldsm_x4(bf[0][0], bf[0][1], bf[1][0], bf[1][1],
                    KsBase + ((wn * 16 + b_nr) * KPITCH + kc + b_koff) * 4);
            #pragma unroll
            for (int nt = 0; nt < 2; nt++) {
                if (s < 8)
                    mma_tf32(accC[nt][0], accC[nt][1], accC[nt][2], accC[nt][3],
                             afr[s][0], afr[s][1], afr[s][2], afr[s][3],
                             bf[nt][0], bf[nt][1]);
                else
                    mma_tf32(accQ[nt][0], accQ[nt][1], accQ[nt][2], accQ[nt][3],
                             afr[s][0], afr[s][1], afr[s][2], afr[s][3],
                             bf[nt][0], bf[nt][1]);
            }
        }
        #pragma unroll
        for (int nt = 0; nt < 2; nt++) {
            int r  = wm * 16 + g;
            int cl = wn * 16 + nt * 8 + tg * 2;
            #pragma unroll
            for (int hrow = 0; hrow < 2; hrow++) {
                int rr = r + hrow * 8;
                int base = rr + 767 - j0 - cl;
                float e0 = entT[base];
                float e1 = entT[base - 1];
                float2 st;
                st.x = accC[nt][hrow * 2]     + e0 * accQ[nt][hrow * 2];
                st.y = accC[nt][hrow * 2 + 1] + e1 * accQ[nt][hrow * 2 + 1];
                *(float2*)&P[rr * PROW + j0 + cl] = st;
            }
        }
        __syncthreads();
        if (jc + 1 < 12) {
            #pragma unroll
            for (int it = 0; it < 2; it++) {
                int fid = tid + ATHREADS * it;
                int r = fid >> 4, c4 = (fid & 15) * 4;
                *(uint4*)&Ks[r * KPITCH + c4] =
                    make_uint4(f2tf32(rcA[it].x), f2tf32(rcA[it].y),
                               f2tf32(rcA[it].z), f2tf32(rcA[it].w));
            }
            if (tid < 256)
                *(uint4*)&Ks[sF_r * KPITCH + 64 + sF_c4] =
                    make_uint4(f2tf32(rqA.x), f2tf32(rqA.y),
                               f2tf32(rqA.z), f2tf32(rqA.w));
        }
        __syncthreads();
        rcA[0] = rcB[0]; rcA[1] = rcB[1]; rqA = rqB;
    }

    float4 vA[2], vB[2];
    #pragma unroll
    for (int it = 0; it < 2; it++) {
        int fid = tid + ATHREADS * it;
        int d = fid >> 4, c4 = (fid & 15) * 4;
        vA[it] = *(const float4*)&Vtp[(size_t)d * SS + c4];
    }

    for (int rr = wid; rr < 64; rr += 16) {
        float4* row4 = (float4*)(P + rr * PROW);
        float4 v[6];
        float m = -1e30f;
        #pragma unroll
        for (int u = 0; u < 6; u++) {
            v[u] = row4[lane + u * 32];
            m = fmaxf(m, fmaxf(fmaxf(v[u].x, v[u].y), fmaxf(v[u].z, v[u].w)));
        }
        #pragma unroll
        for (int o = 16; o; o >>= 1) m = fmaxf(m, __shfl_xor_sync(0xffffffffu, m, o));
        float ssum = 0.f;
        #pragma unroll
        for (int u = 0; u < 6; u++) {
            v[u].x = __expf(v[u].x - m); v[u].y = __expf(v[u].y - m);
            v[u].z = __expf(v[u].z - m); v[u].w = __expf(v[u].w - m);
            ssum += (v[u].x + v[u].y) + (v[u].z + v[u].w);
        }
        #pragma unroll
        for (int o = 16; o; o >>= 1) ssum += __shfl_xor_sync(0xffffffffu, ssum, o);
        float inv = __frcp_rn(ssum);
        float* o2row = o2p + (size_t)(i0 + rr) * SS;
        #pragma unroll
        for (int u = 0; u < 6; u++) {
            float4 t;
            t.x = __uint_as_float(f2tf32(v[u].x * inv));
            t.y = __uint_as_float(f2tf32(v[u].y * inv));
            t.z = __uint_as_float(f2tf32(v[u].z * inv));
            t.w = __uint_as_float(f2tf32(v[u].w * inv));
            row4[lane + u * 32] = t;
            red_add_v4(o2row + (lane + u * 32) * 4,
                       t.x * (1.0f / HH), t.y * (1.0f / HH),
                       t.z * (1.0f / HH), t.w * (1.0f / HH));
        }
    }
    __syncthreads();

    float acc[2][4] = {};
    {
        #pragma unroll
        for (int it = 0; it < 2; it++) {
            int fid = tid + ATHREADS * it;
            int d = fid >> 4, c4 = (fid & 15) * 4;
            *(uint4*)&Vs0[d * VPITCH + c4] =
                make_uint4(f2tf32(vA[it].x), f2tf32(vA[it].y),
                           f2tf32(vA[it].z), f2tf32(vA[it].w));
        }
        #pragma unroll
        for (int it = 0; it < 2; it++) {
            int fid = tid + ATHREADS * it;
            int d = fid >> 4, c4 = (fid & 15) * 4;
            vA[it] = *(const float4*)&Vtp[(size_t)d * SS + 64 + c4];
        }
        __syncthreads();
    }
    for (int c = 0; c < 12; c++) {
        int k0 = c * 64;
        unsigned curB = (c & 1) ? VsBase1 : VsBase0;
        unsigned* nxt = (c & 1) ? Vs0 : Vs1;
        if (c + 2 < 12) {
            int kn = k0 + 128;
            #pragma unroll
            for (int it = 0; it < 2; it++) {
                int fid = tid + ATHREADS * it;
                int d = fid >> 4, c4 = (fid & 15) * 4;
                vB[it] = *(const float4*)&Vtp[(size_t)d * SS + kn + c4];
            }
        }
        #pragma unroll
        for (int s = 0; s < 8; s++) {
            int kc = s * 8;
            unsigned af[4];
            ldsm_x4(af[0], af[1], af[2], af[3],
                    PBase + ((wm * 16 + a_row) * PROW + k0 + kc + a_koff) * 4);
            unsigned bf[2][2];
            ldsm_x4(bf[0][0], bf[0][1], bf[1][0], bf[1][1],
                    curB + ((wn * 16 + b_nr) * VPITCH + kc + b_koff) * 4);
            #pragma unroll
            for (int nt = 0; nt < 2; nt++)
                mma_tf32(acc[nt][0], acc[nt][1], acc[nt][2], acc[nt][3],
                         af[0], af[1], af[2], af[3], bf[nt][0], bf[nt][1]);
        }
        if (c + 1 < 12) {
            #pragma unroll
            for (int it = 0; it < 2; it++) {
                int fid = tid + ATHREADS * it;
                int d = fid >> 4, c4 = (fid & 15) * 4;
                *(uint4*)&nxt[d * VPITCH + c4] =
                    make_uint4(f2tf32(vA[it].x), f2tf32(vA[it].y),
                               f2tf32(vA[it].z), f2tf32(vA[it].w));
            }
        }
        __syncthreads();
        vA[0] = vB[0]; vA[1] = vB[1];
    }
    #pragma unroll
    for (int nt = 0; nt < 2; nt++) {
        int r = wm * 16 + g;
        int d0 = wn * 16 + nt * 8 + tg * 2;
        #pragma unroll
        for (int hrow = 0; hrow < 2; hrow++) {
            int s_ = i0 + r + hrow * 8;
            *(float2*)&g_att[(size_t)(b * SS + s_) * DDIM + h * HDIM + d0] =
                make_float2(acc[nt][hrow * 2], acc[nt][hrow * 2 + 1]);
        }
    }
}

// ---------------- launch -----------------------------------------------------
extern "C" void kernel_launch(void* const* d_in, const int* in_sizes, int n_in,
                              void* d_out, int out_size) {
    const float* query = (const float*)d_in[0];
    const float* key   = (const float*)d_in[1];
    const float* value = (const float*)d_in[2];
    const float* Wq = (const float*)d_in[3];
    const float* bq = (const float*)d_in[4];
    const float* Wk = (const float*)d_in[5];
    const float* bk = (const float*)d_in[6];
    const float* Wv = (const float*)d_in[7];
    const float* bv = (const float*)d_in[8];
    const float* Wo = (const float*)d_in[9];
    const float* bo = (const float*)d_in[10];
    const float* qmapW = (const float*)d_in[11];
    const float* qmapb = (const float*)d_in[12];
    const float* qw    = (const float*)d_in[13];
    const float* ph    = (const float*)d_in[14];
    const float* es    = (const float*)d_in[15];

    float* out  = (float*)d_out;
    float* out2 = out + (size_t)MM * DDIM;

    proj_kernel<<<dim3(DDIM / 128, MM / 128, 3), 256>>>(query, key, value,
                                                        Wq, bq, Wk, bk, Wv, bv);
    {   // qfeat also zero-fills d_out (out + out2) ahead of attn/outproj
        int nrows = 2 * BHn * SS;
        qfeat_kernel<<<nrows / 8, 256>>>(qmapW, qmapb, qw, ph, es, out);
    }
    {
        size_t smem = (size_t)64 * PROW * 4 + (size_t)2 * 64 * VPITCH * 4; // 232448
        cudaFuncSetAttribute(attn_kernel,
                             cudaFuncAttributeMaxDynamicSharedMemorySize, (int)smem);
        attn_kernel<<<dim3(SS / 64, BHn), ATHREADS, smem>>>(es, out2);
    }
    outproj_kernel<<<dim3(DDIM / 128, MM / 128, 2), 256>>>(Wo, bo, out);
}

// round 16
// speedup vs baseline: 1.2195x; 1.0414x over previous
#include <cuda_runtime.h>
#include <math.h>

#define BB   2
#define SS   768
#define DDIM 1024
#define HH   16
#define HDIM 64
#define NQh  8
#define NF   16
#define BHn  (BB*HH)     // 32
#define MM   (BB*SS)     // 1536
#define PROW 772         // 772 % 32 == 4 -> conflict-free ldmatrix rows
#define SPITCH 20
#define KPITCH 84        // 84 % 32 == 20 -> conflict-free
#define VPITCH 68        // 68 % 32 == 4  -> conflict-free
#define ENTN 831
#define ATHREADS 512

// ---------------- scratch ----------------------------------------------------
__device__ float g_Q[BHn*SS*HDIM];      // [bh][s][d]
__device__ float g_K[BHn*SS*HDIM];      // [bh][s][d]
__device__ float g_V[BHn*SS*HDIM];      // [bh][d][s]  (TRANSPOSED)
__device__ float g_fQ[BHn*SS*NF];
__device__ float g_fK[BHn*SS*NF];
__device__ float g_att[MM*DDIM];

// ---------------- helpers ----------------------------------------------------
__device__ __forceinline__ unsigned f2tf32(float f) {
    unsigned u;
    asm("cvt.rna.tf32.f32 %0, %1;" : "=r"(u) : "f"(f));
    return u;
}

__device__ __forceinline__ void mma_tf32(float& c0, float& c1, float& c2, float& c3,
                                         unsigned a0, unsigned a1, unsigned a2, unsigned a3,
                                         unsigned b0, unsigned b1) {
    asm volatile("mma.sync.aligned.m16n8k8.row.col.f32.tf32.tf32.f32 "
                 "{%0,%1,%2,%3}, {%4,%5,%6,%7}, {%8,%9}, {%0,%1,%2,%3};\n"
                 : "+f"(c0), "+f"(c1), "+f"(c2), "+f"(c3)
                 : "r"(a0), "r"(a1), "r"(a2), "r"(a3), "r"(b0), "r"(b1));
}

__device__ __forceinline__ void ldsm_x4(unsigned& r0, unsigned& r1,
                                        unsigned& r2, unsigned& r3, unsigned addr) {
    asm volatile("ldmatrix.sync.aligned.m8n8.x4.shared.b16 {%0,%1,%2,%3}, [%4];"
                 : "=r"(r0), "=r"(r1), "=r"(r2), "=r"(r3) : "r"(addr));
}

__device__ __forceinline__ void red_add_v4(float* p, float x, float y, float z, float w) {
    asm volatile("red.global.add.v4.f32 [%0], {%1,%2,%3,%4};"
                 :: "l"(p), "f"(x), "f"(y), "f"(z), "f"(w) : "memory");
}

__device__ __forceinline__ void red_add_v2(float* p, float x, float y) {
    asm volatile("red.global.add.v2.f32 [%0], {%1,%2};"
                 :: "l"(p), "f"(x), "f"(y) : "memory");
}

// ============================================================================
// tf32 GEMM core: 128x128 tile, 8 warps, ldmatrix fragments, ping-pong smem.
// K range [KBASE, KBASE + NCHUNK*16).
// ============================================================================
#define GEMM_BODY(LOAD_A0, LOAD_A1, LOAD_B, NCHUNK, KBASE)                       \
    float acc[4][4][4] = {};                                                     \
    int tid = threadIdx.x;                                                       \
    int wid = tid >> 5, lane = tid & 31;                                         \
    int wm = wid & 1, wnw = wid >> 1;                                            \
    int ar = tid >> 2, ac = (tid & 3) * 4;                                       \
    int bn = tid & 127, bk0 = (tid >> 7) * 8;                                    \
    int a_row = lane & 15, a_koff = (lane >> 4) * 4;                             \
    int b_nr  = (lane & 7) + ((lane >> 4) << 3);                                 \
    int b_koff = ((lane >> 3) & 1) * 4;                                          \
    unsigned aBase0 = (unsigned)__cvta_generic_to_shared(As0);                   \
    unsigned aBase1 = (unsigned)__cvta_generic_to_shared(As1);                   \
    unsigned bBase0 = (unsigned)__cvta_generic_to_shared(Bs0);                   \
    unsigned bBase1 = (unsigned)__cvta_generic_to_shared(Bs1);                   \
    float4 pa0, pa1; float pb[8];                                                \
    { int kg = (KBASE);                                                          \
      pa0 = LOAD_A0(kg); pa1 = LOAD_A1(kg);                                      \
      _Pragma("unroll") for (int j = 0; j < 8; j++) pb[j] = LOAD_B(kg, j); }     \
    { unsigned* As = As0; unsigned* Bs = Bs0;                                    \
      *(uint4*)&As[ar * SPITCH + ac] =                                           \
          make_uint4(f2tf32(pa0.x), f2tf32(pa0.y), f2tf32(pa0.z), f2tf32(pa0.w));\
      *(uint4*)&As[(ar + 64) * SPITCH + ac] =                                    \
          make_uint4(f2tf32(pa1.x), f2tf32(pa1.y), f2tf32(pa1.z), f2tf32(pa1.w));\
      *(uint4*)&Bs[bn * SPITCH + bk0] =                                          \
          make_uint4(f2tf32(pb[0]), f2tf32(pb[1]), f2tf32(pb[2]), f2tf32(pb[3]));\
      *(uint4*)&Bs[bn * SPITCH + bk0 + 4] =                                      \
          make_uint4(f2tf32(pb[4]), f2tf32(pb[5]), f2tf32(pb[6]), f2tf32(pb[7]));}\
    __syncthreads();                                                             \
    for (int ch = 0; ch < (NCHUNK); ch++) {                                      \
        int buf = ch & 1;                                                        \
        if (ch + 1 < (NCHUNK)) {                                                 \
            int kg = (KBASE) + (ch + 1) * 16;                                    \
            pa0 = LOAD_A0(kg); pa1 = LOAD_A1(kg);                                \
            _Pragma("unroll") for (int j = 0; j < 8; j++) pb[j] = LOAD_B(kg, j); \
        }                                                                        \
        unsigned aB = buf ? aBase1 : aBase0;                                     \
        unsigned bB = buf ? bBase1 : bBase0;                                     \
        _Pragma("unroll")                                                        \
        for (int ks = 0; ks < 2; ks++) {                                         \
            int kc = ks * 8;                                                     \
            unsigned af[4][4];                                                   \
            _Pragma("unroll")                                                    \
            for (int mt = 0; mt < 4; mt++)                                       \
                ldsm_x4(af[mt][0], af[mt][1], af[mt][2], af[mt][3],              \
                    aB + ((wm * 64 + mt * 16 + a_row) * SPITCH + kc + a_koff) * 4);\
            unsigned bf[4][2];                                                   \
            _Pragma("unroll")                                                    \
            for (int p = 0; p < 2; p++)                                          \
                ldsm_x4(bf[2 * p][0], bf[2 * p][1], bf[2 * p + 1][0],            \
                        bf[2 * p + 1][1],                                        \
                    bB + ((wnw * 32 + p * 16 + b_nr) * SPITCH + kc + b_koff) * 4);\
            _Pragma("unroll")                                                    \
            for (int mt = 0; mt < 4; mt++)                                       \
                _Pragma("unroll")                                                \
                for (int nt = 0; nt < 4; nt++)                                   \
                    mma_tf32(acc[mt][nt][0], acc[mt][nt][1],                     \
                             acc[mt][nt][2], acc[mt][nt][3],                     \
                             af[mt][0], af[mt][1], af[mt][2], af[mt][3],         \
                             bf[nt][0], bf[nt][1]);                              \
        }                                                                        \
        if (ch + 1 < (NCHUNK)) {                                                 \
            unsigned* As = buf ? As0 : As1;                                      \
            unsigned* Bs = buf ? Bs0 : Bs1;                                      \
            *(uint4*)&As[ar * SPITCH + ac] =                                     \
                make_uint4(f2tf32(pa0.x), f2tf32(pa0.y), f2tf32(pa0.z), f2tf32(pa0.w));\
            *(uint4*)&As[(ar + 64) * SPITCH + ac] =                              \
                make_uint4(f2tf32(pa1.x), f2tf32(pa1.y), f2tf32(pa1.z), f2tf32(pa1.w));\
            *(uint4*)&Bs[bn * SPITCH + bk0] =                                    \
                make_uint4(f2tf32(pb[0]), f2tf32(pb[1]), f2tf32(pb[2]), f2tf32(pb[3]));\
            *(uint4*)&Bs[bn * SPITCH + bk0 + 4] =                                \
                make_uint4(f2tf32(pb[4]), f2tf32(pb[5]), f2tf32(pb[6]), f2tf32(pb[7]));\
        }                                                                        \
        __syncthreads();                                                         \
    }

// ---------------- fused QKV projection (full K) ------------------------------
__global__ __launch_bounds__(256, 2) void proj_kernel(
        const float* __restrict__ q, const float* __restrict__ k,
        const float* __restrict__ v,
        const float* __restrict__ Wq, const float* __restrict__ bq,
        const float* __restrict__ Wk, const float* __restrict__ bk,
        const float* __restrict__ Wv, const float* __restrict__ bv) {
    int which = blockIdx.z;
    const float* A    = (which == 0) ? q  : (which == 1) ? k  : v;
    const float* W    = (which == 0) ? Wq : (which == 1) ? Wk : Wv;
    const float* bias = (which == 0) ? bq : (which == 1) ? bk : bv;
    float*       out  = (which == 0) ? g_Q : (which == 1) ? g_K : g_V;

    __shared__ unsigned As0[128 * SPITCH], As1[128 * SPITCH];
    __shared__ unsigned Bs0[128 * SPITCH], Bs1[128 * SPITCH];
    int row0 = blockIdx.y * 128, col0 = blockIdx.x * 128;

#define LA0(kg) (*(const float4*)&A[(size_t)(row0 + ar) * DDIM + (kg) + ac])
#define LA1(kg) (*(const float4*)&A[(size_t)(row0 + 64 + ar) * DDIM + (kg) + ac])
#define LB(kg, j) (W[(size_t)((kg) + bk0 + (j)) * DDIM + col0 + bn])
    GEMM_BODY(LA0, LA1, LB, DDIM / 16, 0)
#undef LA0
#undef LA1
#undef LB

    int g = lane >> 2, tg = lane & 3;
    #pragma unroll
    for (int mt = 0; mt < 4; mt++)
        #pragma unroll
        for (int nt = 0; nt < 4; nt++) {
            int gm = row0 + wm * 64 + mt * 16 + g;
            int gn = col0 + wnw * 32 + nt * 8 + tg * 2;
            #pragma unroll
            for (int hrow = 0; hrow < 2; hrow++) {
                int m = gm + hrow * 8;
                int b = m / SS, s = m % SS;
                int h = gn >> 6, d = gn & 63;
                if (which == 2) {   // V transposed: [bh][d][s]
                    #pragma unroll
                    for (int j = 0; j < 2; j++)
                        out[((size_t)(b * HH + h) * HDIM + d + j) * SS + s] =
                            acc[mt][nt][hrow * 2 + j] + bias[gn + j];
                } else {            // Q/K: [bh][s][d]
                    float2 st;
                    st.x = acc[mt][nt][hrow * 2]     + bias[gn];
                    st.y = acc[mt][nt][hrow * 2 + 1] + bias[gn + 1];
                    *(float2*)&out[((size_t)(b * HH + h) * SS + s) * HDIM + d] = st;
                }
            }
        }
}

// ---------------- outproj, split-K=3 (22/21/21 chunks; red.add into out) -----
__global__ __launch_bounds__(256, 2) void outproj_kernel(const float* __restrict__ Wo,
                                                         const float* __restrict__ bo,
                                                         float* __restrict__ out) {
    __shared__ unsigned As0[128 * SPITCH], As1[128 * SPITCH];
    __shared__ unsigned Bs0[128 * SPITCH], Bs1[128 * SPITCH];
    int row0 = blockIdx.y * 128, col0 = blockIdx.x * 128;
    int z = blockIdx.z;
    int kbase = (z == 0) ? 0 : (z == 1) ? 352 : 688;
    int nch   = (z == 0) ? 22 : 21;

#define LA0(kg) (*(const float4*)&g_att[(size_t)(row0 + ar) * DDIM + (kg) + ac])
#define LA1(kg) (*(const float4*)&g_att[(size_t)(row0 + 64 + ar) * DDIM + (kg) + ac])
#define LB(kg, j) (Wo[(size_t)((kg) + bk0 + (j)) * DDIM + col0 + bn])
    GEMM_BODY(LA0, LA1, LB, nch, kbase)
#undef LA0
#undef LA1
#undef LB

    int g = lane >> 2, tg = lane & 3;
    bool addb = (z == 0);
    #pragma unroll
    for (int mt = 0; mt < 4; mt++)
        #pragma unroll
        for (int nt = 0; nt < 4; nt++) {
            int gm = row0 + wm * 64 + mt * 16 + g;
            int gn = col0 + wnw * 32 + nt * 8 + tg * 2;
            #pragma unroll
            for (int hrow = 0; hrow < 2; hrow++) {
                int m = gm + hrow * 8;
                float x = acc[mt][nt][hrow * 2]     + (addb ? bo[gn]     : 0.f);
                float y = acc[mt][nt][hrow * 2 + 1] + (addb ? bo[gn + 1] : 0.f);
                red_add_v2(&out[(size_t)m * DDIM + gn], x, y);
            }
        }
}

// ---------------- quantum features (warp-per-row) + output zero-fill ---------
__global__ __launch_bounds__(256) void qfeat_kernel(
        const float* __restrict__ qmapW, const float* __restrict__ qmapb,
        const float* __restrict__ qw, const float* __restrict__ ph,
        const float* __restrict__ es_ptr, float* __restrict__ outbuf) {
    {
        int gtid = blockIdx.x * blockDim.x + threadIdx.x;
        int n1 = MM * DDIM / 4;
        int n2 = BB * SS * SS / 4;
        if (gtid < n1)
            ((float4*)outbuf)[gtid] = make_float4(0.f, 0.f, 0.f, 0.f);
        int g2 = gtid - n1;
        if (g2 >= 0 && g2 < n2)
            ((float4*)(outbuf + (size_t)MM * DDIM))[g2] = make_float4(0.f, 0.f, 0.f, 0.f);
    }
    int gw   = (blockIdx.x * blockDim.x + threadIdx.x) >> 5;
    int lane = threadIdx.x & 31;
    if (gw >= 2 * BHn * SS) return;
    int side = gw / (BHn * SS);
    int r    = gw % (BHn * SS);
    int h    = (r / SS) % HH;
    const float* row = ((side == 0) ? g_Q : g_K) + (size_t)r * HDIM;
    float rv0 = row[lane], rv1 = row[lane + 32];

    float mydot = 0.f;
    #pragma unroll
    for (int n = 0; n < NQh; n++) {
        float p = rv0 * qmapW[lane * NQh + n] + rv1 * qmapW[(lane + 32) * NQh + n];
        #pragma unroll
        for (int o = 16; o; o >>= 1) p += __shfl_xor_sync(0xffffffffu, p, o);
        if (lane == n) mydot = p;
    }
    if (lane < NQh) {
        float a = tanhf(mydot + qmapb[lane]);
        float s, c;
        if (side == 0) {
            float mix = 1.f / (1.f + __expf(-*es_ptr));
            float w = (1.f / (1.f + __expf(-qw[h * NQh + lane]))) * (1.0f / NQh) * mix;
            sincosf(a + ph[h * NQh + lane], &s, &c);
            g_fQ[(size_t)r * NF + lane]       = w * c;
            g_fQ[(size_t)r * NF + NQh + lane] = w * s;
        } else {
            sincosf(a, &s, &c);
            g_fK[(size_t)r * NF + lane]       = c;
            g_fK[(size_t)r * NF + NQh + lane] = s;
        }
    }
}

// ---------------- fused attention (512 thr; quantum-skip for far tiles) -----
__global__ __launch_bounds__(ATHREADS) void attn_kernel(const float* __restrict__ es_ptr,
                                                        float* __restrict__ out2) {
    extern __shared__ float P[];                       // [64][PROW]
    unsigned* Ks   = (unsigned*)(P + 64 * PROW);       // phase 1
    float*    entT = (float*)(Ks + 64 * KPITCH);       // phase 1 LUT
    unsigned* Vs0  = (unsigned*)(P + 64 * PROW);       // phase 3
    unsigned* Vs1  = Vs0 + 64 * VPITCH;

    int bh = blockIdx.y;
    int b = bh >> 4, h = bh & 15;
    int ic = blockIdx.x;
    int i0 = ic * 64;
    const float* Qp  = g_Q  + (size_t)bh * SS * HDIM;
    const float* Kp  = g_K  + (size_t)bh * SS * HDIM;
    const float* Vtp = g_V  + (size_t)bh * HDIM * SS;  // [d][s]
    const float* Fqp = g_fQ + (size_t)bh * SS * NF;
    const float* Fkp = g_fK + (size_t)bh * SS * NF;
    float* o2p = out2 + (size_t)b * SS * SS;

    int tid = threadIdx.x;
    int wid = tid >> 5, lane = tid & 31;
    int wm = wid & 3, wn = wid >> 2;                   // 4m x 4n
    int g = lane >> 2, tg = lane & 3;
    int a_row = lane & 15, a_koff = (lane >> 4) * 4;
    int b_nr  = (lane & 7) + ((lane >> 4) << 3);
    int b_koff = ((lane >> 3) & 1) * 4;
    unsigned PBase   = (unsigned)__cvta_generic_to_shared(P);
    unsigned KsBase  = (unsigned)__cvta_generic_to_shared(Ks);
    unsigned VsBase0 = (unsigned)__cvta_generic_to_shared(Vs0);
    unsigned VsBase1 = (unsigned)__cvta_generic_to_shared(Vs1);

    float es  = *es_ptr;
    float mix = 1.f / (1.f + __expf(-es));
    float ca  = (1.f - mix) * 0.125f;

    for (int t = tid; t < ENTN; t += ATHREADS)
        entT[t] = __expf(-0.1f * fabsf((float)(i0 - 767 + t)));

    int sF_r = tid >> 2, sF_c4 = (tid & 3) * 4;

    {
        #pragma unroll
        for (int it = 0; it < 2; it++) {
            int fid = tid + ATHREADS * it;
            int r = fid >> 4, c4 = (fid & 15) * 4;
            float4 f = *(const float4*)&Qp[(size_t)(i0 + r) * HDIM + c4];
            *(uint4*)&Ks[r * KPITCH + c4] =
                make_uint4(f2tf32(ca * f.x), f2tf32(ca * f.y),
                           f2tf32(ca * f.z), f2tf32(ca * f.w));
        }
        if (tid < 256) {
            float4 f = *(const float4*)&Fqp[(size_t)(i0 + sF_r) * NF + sF_c4];
            *(uint4*)&Ks[sF_r * KPITCH + 64 + sF_c4] =
                make_uint4(f2tf32(f.x), f2tf32(f.y), f2tf32(f.z), f2tf32(f.w));
        }
    }
    __syncthreads();
    unsigned afr[10][4];
    #pragma unroll
    for (int s = 0; s < 10; s++) {
        int r = wm * 16 + g, c = s * 8 + tg;
        afr[s][0] = Ks[r * KPITCH + c];
        afr[s][1] = Ks[(r + 8) * KPITCH + c];
        afr[s][2] = Ks[r * KPITCH + c + 4];
        afr[s][3] = Ks[(r + 8) * KPITCH + c + 4];
    }
    __syncthreads();

    // ---- phase 1: scores over 12 K-chunks (depth-2 prefetch) ---------------
    float4 rcA[2], rqA, rcB[2], rqB;
    {
        #pragma unroll
        for (int it = 0; it < 2; it++) {
            int fid = tid + ATHREADS * it;
            int r = fid >> 4, c4 = (fid & 15) * 4;
            rcA[it] = *(const float4*)&Kp[(size_t)r * HDIM + c4];
        }
        if (tid < 256)
            rqA = *(const float4*)&Fkp[(size_t)sF_r * NF + sF_c4];
        #pragma unroll
        for (int it = 0; it < 2; it++) {
            int fid = tid + ATHREADS * it;
            int r = fid >> 4, c4 = (fid & 15) * 4;
            *(uint4*)&Ks[r * KPITCH + c4] =
                make_uint4(f2tf32(rcA[it].x), f2tf32(rcA[it].y),
                           f2tf32(rcA[it].z), f2tf32(rcA[it].w));
        }
        if (tid < 256)
            *(uint4*)&Ks[sF_r * KPITCH + 64 + sF_c4] =
                make_uint4(f2tf32(rqA.x), f2tf32(rqA.y), f2tf32(rqA.z), f2tf32(rqA.w));
        #pragma unroll
        for (int it = 0; it < 2; it++) {
            int fid = tid + ATHREADS * it;
            int r = fid >> 4, c4 = (fid & 15) * 4;
            rcA[it] = *(const float4*)&Kp[(size_t)(64 + r) * HDIM + c4];
        }
        if (tid < 256)
            rqA = *(const float4*)&Fkp[(size_t)(64 + sF_r) * NF + sF_c4];
        __syncthreads();
    }
    for (int jc = 0; jc < 12; jc++) {
        int j0 = jc * 64;
        int dj = jc - ic;
        bool useQ = (dj <= 2) && (dj >= -2);    // ent <= 2.5e-6 beyond this
        if (jc + 2 < 12) {
            int jn = j0 + 128;
            #pragma unroll
            for (int it = 0; it < 2; it++) {
                int fid = tid + ATHREADS * it;
                int r = fid >> 4, c4 = (fid & 15) * 4;
                rcB[it] = *(const float4*)&Kp[(size_t)(jn + r) * HDIM + c4];
            }
            if (tid < 256)
                rqB = *(const float4*)&Fkp[(size_t)(jn + sF_r) * NF + sF_c4];
        }
        float accC[2][4] = {}, accQ[2][4] = {};
        #pragma unroll
        for (int s = 0; s < 8; s++) {           // classical: always
            int kc = s * 8;
            unsigned bf[2][2];
            ldsm_x4(bf[0][0], bf[0][1], bf[1][0], bf[1][1],
                    KsBase + ((wn * 16 + b_nr) * KPITCH + kc + b_koff) * 4);
            #pragma unroll
            for (int nt = 0; nt < 2; nt++)
                mma_tf32(accC[nt][0], accC[nt][1], accC[nt][2], accC[nt][3],
                         afr[s][0], afr[s][1], afr[s][2], afr[s][3],
                         bf[nt][0], bf[nt][1]);
        }
        if (useQ) {                             // quantum: near tiles only
            #pragma unroll
            for (int s = 8; s < 10; s++) {
                int kc = s * 8;
                unsigned bf[2][2];
                ldsm_x4(bf[0][0], bf[0][1], bf[1][0], bf[1][1],
                        KsBase + ((wn * 16 + b_nr) * KPITCH + kc + b_koff) * 4);
                #pragma unroll
                for (int nt = 0; nt < 2; nt++)
                    mma_tf32(accQ[nt][0], accQ[nt][1], accQ[nt][2], accQ[nt][3],
                             afr[s][0], afr[s][1], afr[s][2], afr[s][3],
                             bf[nt][0], bf[nt][1]);
            }
        }
        #pragma unroll
        for (int nt = 0; nt < 2; nt++) {
            int r  = wm * 16 + g;
            int cl = wn * 16 + nt * 8 + tg * 2;
            #pragma unroll
            for (int hrow = 0; hrow < 2; hrow++) {
                int rr = r + hrow * 8;
                float2 st;
                if (useQ) {
                    int base = rr + 767 - j0 - cl;
                    st.x = accC[nt][hrow * 2]     + entT[base]     * accQ[nt][hrow * 2];
                    st.y = accC[nt][hrow * 2 + 1] + entT[base - 1] * accQ[nt][hrow * 2 + 1];
                } else {
                    st.x = accC[nt][hrow * 2];
                    st.y = accC[nt][hrow * 2 + 1];
                }
                *(float2*)&P[rr * PROW + j0 + cl] = st;
            }
        }
        __syncthreads();
        if (jc + 1 < 12) {
            #pragma unroll
            for (int it = 0; it < 2; it++) {
                int fid = tid + ATHREADS * it;
                int r = fid >> 4, c4 = (fid & 15) * 4;
                *(uint4*)&Ks[r * KPITCH + c4] =
                    make_uint4(f2tf32(rcA[it].x), f2tf32(rcA[it].y),
                               f2tf32(rcA[it].z), f2tf32(rcA[it].w));
            }
            if (tid < 256)
                *(uint4*)&Ks[sF_r * KPITCH + 64 + sF_c4] =
                    make_uint4(f2tf32(rqA.x), f2tf32(rqA.y),
                               f2tf32(rqA.z), f2tf32(rqA.w));
        }
        __syncthreads();
        rcA[0] = rcB[0]; rcA[1] = rcB[1]; rqA = rqB;
    }

    float4 vA[2], vB[2];
    #pragma unroll
    for (int it = 0; it < 2; it++) {
        int fid = tid + ATHREADS * it;
        int d = fid >> 4, c4 = (fid & 15) * 4;
        vA[it] = *(const float4*)&Vtp[(size_t)d * SS + c4];
    }

    for (int rr = wid; rr < 64; rr += 16) {
        float4* row4 = (float4*)(P + rr * PROW);
        float4 v[6];
        float m = -1e30f;
        #pragma unroll
        for (int u = 0; u < 6; u++) {
            v[u] = row4[lane + u * 32];
            m = fmaxf(m, fmaxf(fmaxf(v[u].x, v[u].y), fmaxf(v[u].z, v[u].w)));
        }
        #pragma unroll
        for (int o = 16; o; o >>= 1) m = fmaxf(m, __shfl_xor_sync(0xffffffffu, m, o));
        float ssum = 0.f;
        #pragma unroll
        for (int u = 0; u < 6; u++) {
            v[u].x = __expf(v[u].x - m); v[u].y = __expf(v[u].y - m);
            v[u].z = __expf(v[u].z - m); v[u].w = __expf(v[u].w - m);
            ssum += (v[u].x + v[u].y) + (v[u].z + v[u].w);
        }
        #pragma unroll
        for (int o = 16; o; o >>= 1) ssum += __shfl_xor_sync(0xffffffffu, ssum, o);
        float inv = __frcp_rn(ssum);
        float* o2row = o2p + (size_t)(i0 + rr) * SS;
        #pragma unroll
        for (int u = 0; u < 6; u++) {
            float4 t;
            t.x = __uint_as_float(f2tf32(v[u].x * inv));
            t.y = __uint_as_float(f2tf32(v[u].y * inv));
            t.z = __uint_as_float(f2tf32(v[u].z * inv));
            t.w = __uint_as_float(f2tf32(v[u].w * inv));
            row4[lane + u * 32] = t;
            red_add_v4(o2row + (lane + u * 32) * 4,
                       t.x * (1.0f / HH), t.y * (1.0f / HH),
                       t.z * (1.0f / HH), t.w * (1.0f / HH));
        }
    }
    __syncthreads();

    float acc[2][4] = {};
    {
        #pragma unroll
        for (int it = 0; it < 2; it++) {
            int fid = tid + ATHREADS * it;
            int d = fid >> 4, c4 = (fid & 15) * 4;
            *(uint4*)&Vs0[d * VPITCH + c4] =
                make_uint4(f2tf32(vA[it].x), f2tf32(vA[it].y),
                           f2tf32(vA[it].z), f2tf32(vA[it].w));
        }
        #pragma unroll
        for (int it = 0; it < 2; it++) {
            int fid = tid + ATHREADS * it;
            int d = fid >> 4, c4 = (fid & 15) * 4;
            vA[it] = *(const float4*)&Vtp[(size_t)d * SS + 64 + c4];
        }
        __syncthreads();
    }
    for (int c = 0; c < 12; c++) {
        int k0 = c * 64;
        unsigned curB = (c & 1) ? VsBase1 : VsBase0;
        unsigned* nxt = (c & 1) ? Vs0 : Vs1;
        if (c + 2 < 12) {
            int kn = k0 + 128;
            #pragma unroll
            for (int it = 0; it < 2; it++) {
                int fid = tid + ATHREADS * it;
                int d = fid >> 4, c4 = (fid & 15) * 4;
                vB[it] = *(const float4*)&Vtp[(size_t)d * SS + kn + c4];
            }
        }
        #pragma unroll
        for (int s = 0; s < 8; s++) {
            int kc = s * 8;
            unsigned af[4];
            ldsm_x4(af[0], af[1], af[2], af[3],
                    PBase + ((wm * 16 + a_row) * PROW + k0 + kc + a_koff) * 4);
            unsigned bf[2][2];
            ldsm_x4(bf[0][0], bf[0][1], bf[1][0], bf[1][1],
                    curB + ((wn * 16 + b_nr) * VPITCH + kc + b_koff) * 4);
            #pragma unroll
            for (int nt = 0; nt < 2; nt++)
                mma_tf32(acc[nt][0], acc[nt][1], acc[nt][2], acc[nt][3],
                         af[0], af[1], af[2], af[3], bf[nt][0], bf[nt][1]);
        }
        if (c + 1 < 12) {
            #pragma unroll
            for (int it = 0; it < 2; it++) {
                int fid = tid + ATHREADS * it;
                int d = fid >> 4, c4 = (fid & 15) * 4;
                *(uint4*)&nxt[d * VPITCH + c4] =
                    make_uint4(f2tf32(vA[it].x), f2tf32(vA[it].y),
                               f2tf32(vA[it].z), f2tf32(vA[it].w));
            }
        }
        __syncthreads();
        vA[0] = vB[0]; vA[1] = vB[1];
    }
    #pragma unroll
    for (int nt = 0; nt < 2; nt++) {
        int r = wm * 16 + g;
        int d0 = wn * 16 + nt * 8 + tg * 2;
        #pragma unroll
        for (int hrow = 0; hrow < 2; hrow++) {
            int s_ = i0 + r + hrow * 8;
            *(float2*)&g_att[(size_t)(b * SS + s_) * DDIM + h * HDIM + d0] =
                make_float2(acc[nt][hrow * 2], acc[nt][hrow * 2 + 1]);
        }
    }
}

// ---------------- launch -----------------------------------------------------
extern "C" void kernel_launch(void* const* d_in, const int* in_sizes, int n_in,
                              void* d_out, int out_size) {
    const float* query = (const float*)d_in[0];
    const float* key   = (const float*)d_in[1];
    const float* value = (const float*)d_in[2];
    const float* Wq = (const float*)d_in[3];
    const float* bq = (const float*)d_in[4];
    const float* Wk = (const float*)d_in[5];
    const float* bk = (const float*)d_in[6];
    const float* Wv = (const float*)d_in[7];
    const float* bv = (const float*)d_in[8];
    const float* Wo = (const float*)d_in[9];
    const float* bo = (const float*)d_in[10];
    const float* qmapW = (const float*)d_in[11];
    const float* qmapb = (const float*)d_in[12];
    const float* qw    = (const float*)d_in[13];
    const float* ph    = (const float*)d_in[14];
    const float* es    = (const float*)d_in[15];

    float* out  = (float*)d_out;
    float* out2 = out + (size_t)MM * DDIM;

    proj_kernel<<<dim3(DDIM / 128, MM / 128, 3), 256>>>(query, key, value,
                                                        Wq, bq, Wk, bk, Wv, bv);
    {   // qfeat also zero-fills d_out (out + out2)
        int nrows = 2 * BHn * SS;
        qfeat_kernel<<<nrows / 8, 256>>>(qmapW, qmapb, qw, ph, es, out);
    }
    {
        size_t smem = (size_t)64 * PROW * 4 + (size_t)2 * 64 * VPITCH * 4; // 232448
        cudaFuncSetAttribute(attn_kernel,
                             cudaFuncAttributeMaxDynamicSharedMemorySize, (int)smem);
        attn_kernel<<<dim3(SS / 64, BHn), ATHREADS, smem>>>(es, out2);
    }
    outproj_kernel<<<dim3(DDIM / 128, MM / 128, 3), 256>>>(Wo, bo, out);
}